// round 13
// baseline (speedup 1.0000x reference)
#include <cuda_runtime.h>
#include <cuda_fp16.h>
#include <cstdint>
#include <math.h>

// Problem constants
#define S_TXT 512
#define S_IMG 2304
#define S_ALL 2816
#define DMODEL 3072
#define NH 24
#define HD 128

// ---------------------------------------------------------------------------
// Static device scratch (allocation-free rule)
// ---------------------------------------------------------------------------
__device__ float g_Q[S_ALL * DMODEL];
__device__ float g_K[S_ALL * DMODEL];

__device__ __half g_Xh[S_ALL * DMODEL];
__device__ __half g_Xl[S_ALL * DMODEL];
__device__ __half g_Qh[S_ALL * DMODEL];
__device__ __half g_Ql[S_ALL * DMODEL];
__device__ __half g_Kh[S_ALL * DMODEL];
__device__ __half g_Kl[S_ALL * DMODEL];
__device__ __half g_Vh[S_ALL * DMODEL];
__device__ __half g_Oh[S_ALL * DMODEL];
__device__ __half g_Ol[S_ALL * DMODEL];
// 8 weight matrices (single fp16 plane): 0=wq 1=wk 2=wv 3=waq 4=wak 5=wav 6=w_out 7=w_add_out
__device__ __half g_Wh[(size_t)8 * DMODEL * DMODEL];

// ---------------------------------------------------------------------------
// helpers
// ---------------------------------------------------------------------------
__device__ __forceinline__ uint32_t smem_u32(const void* p) {
    uint32_t a;
    asm("{ .reg .u64 t; cvta.to.shared.u64 t, %1; cvt.u32.u64 %0, t; }"
        : "=r"(a) : "l"(p));
    return a;
}

__device__ __forceinline__ void cp_async16(uint32_t dst, const void* src) {
    asm volatile("cp.async.cg.shared.global [%0], [%1], 16;"
                 :: "r"(dst), "l"(src));
}
__device__ __forceinline__ void cp_commit() {
    asm volatile("cp.async.commit_group;");
}
template <int N>
__device__ __forceinline__ void cp_wait() {
    asm volatile("cp.async.wait_group %0;" :: "n"(N));
}

__device__ __forceinline__ void ldsm_x4(uint32_t* r, uint32_t addr) {
    asm volatile("ldmatrix.sync.aligned.m8n8.x4.shared.b16 {%0,%1,%2,%3}, [%4];"
                 : "=r"(r[0]), "=r"(r[1]), "=r"(r[2]), "=r"(r[3]) : "r"(addr));
}

__device__ __forceinline__ void ldsm_x4_t(uint32_t* r, uint32_t addr) {
    asm volatile("ldmatrix.sync.aligned.m8n8.x4.trans.shared.b16 {%0,%1,%2,%3}, [%4];"
                 : "=r"(r[0]), "=r"(r[1]), "=r"(r[2]), "=r"(r[3]) : "r"(addr));
}

// fp32-accumulate MMA (hi passes)
__device__ __forceinline__ void mma16816(float* d, const uint32_t* a,
                                         const uint32_t* b) {
    asm volatile(
        "mma.sync.aligned.m16n8k16.row.col.f32.f16.f16.f32 "
        "{%0,%1,%2,%3}, {%4,%5,%6,%7}, {%8,%9}, {%0,%1,%2,%3};"
        : "+f"(d[0]), "+f"(d[1]), "+f"(d[2]), "+f"(d[3])
        : "r"(a[0]), "r"(a[1]), "r"(a[2]), "r"(a[3]), "r"(b[0]), "r"(b[1]));
}

// fp16-accumulate MMA (correction/lo passes; 2x issue rate)
__device__ __forceinline__ void mma16816_h(uint32_t* d, const uint32_t* a,
                                           const uint32_t* b) {
    asm volatile(
        "mma.sync.aligned.m16n8k16.row.col.f16.f16.f16.f16 "
        "{%0,%1}, {%2,%3,%4,%5}, {%6,%7}, {%0,%1};"
        : "+r"(d[0]), "+r"(d[1])
        : "r"(a[0]), "r"(a[1]), "r"(a[2]), "r"(a[3]), "r"(b[0]), "r"(b[1]));
}

// fold a fp16x2-pair accumulator into the fp32 accumulator (same element order)
__device__ __forceinline__ void fold2(float* d, const uint32_t* dl) {
    __half2 h0 = *(const __half2*)&dl[0];
    __half2 h1 = *(const __half2*)&dl[1];
    d[0] += __low2float(h0);  d[1] += __high2float(h0);
    d[2] += __low2float(h1);  d[3] += __high2float(h1);
}

// fp16 hi/lo split of a pair of fp32 values, packed as __half2 words
__device__ __forceinline__ void split_pack2(float f0, float f1,
                                            uint32_t& hi, uint32_t& lo)
{
    __half h0 = __float2half_rn(f0);
    __half h1 = __float2half_rn(f1);
    __half l0 = __float2half_rn(f0 - __half2float(h0));
    __half l1 = __float2half_rn(f1 - __half2float(h1));
    __half2 H = {h0, h1}, L = {l0, l1};
    hi = *(uint32_t*)&H;
    lo = *(uint32_t*)&L;
}

__device__ __forceinline__ uint32_t pack2_h(float f0, float f1)
{
    __half2 H = {__float2half_rn(f0), __float2half_rn(f1)};
    return *(uint32_t*)&H;
}

// ---------------------------------------------------------------------------
// prepass: fp32 -> fp16 hi/lo (X) and fp32 -> fp16 (W)
// ---------------------------------------------------------------------------
__device__ __forceinline__ void split_store4(
    float4 v, __half* hi, __half* lo)
{
    uint32_t h0, h1, l0, l1;
    split_pack2(v.x, v.y, h0, l0);
    split_pack2(v.z, v.w, h1, l1);
    uint2 Hv = {h0, h1}, Lv = {l0, l1};
    *(uint2*)hi = Hv;
    *(uint2*)lo = Lv;
}

__global__ __launch_bounds__(256) void split_x_kernel(
    const float* __restrict__ hid, const float* __restrict__ enc)
{
    size_t i = (size_t)blockIdx.x * blockDim.x + threadIdx.x;
    size_t n4 = (size_t)S_ALL * DMODEL / 4;
    if (i >= n4) return;
    size_t e = i * 4;
    size_t row = e / DMODEL;
    const float* src = (row < S_TXT) ? (enc + e)
                                     : (hid + (e - (size_t)S_TXT * DMODEL));
    split_store4(*(const float4*)src, g_Xh + e, g_Xl + e);
}

__global__ __launch_bounds__(256) void conv_w_kernel(
    const float* __restrict__ w0, const float* __restrict__ w1,
    const float* __restrict__ w2, const float* __restrict__ w3,
    const float* __restrict__ w4, const float* __restrict__ w5,
    const float* __restrict__ w6, const float* __restrict__ w7)
{
    const float* ws[8] = {w0, w1, w2, w3, w4, w5, w6, w7};
    int widx = blockIdx.y;
    size_t i = (size_t)blockIdx.x * blockDim.x + threadIdx.x;
    size_t n4 = (size_t)DMODEL * DMODEL / 4;
    if (i >= n4) return;
    size_t e = i * 4;
    float4 v = *(const float4*)(ws[widx] + e);
    uint2 H = {pack2_h(v.x, v.y), pack2_h(v.z, v.w)};
    *(uint2*)&g_Wh[(size_t)widx * DMODEL * DMODEL + e] = H;
}

// ---------------------------------------------------------------------------
// mma.sync 2-pass fp16 GEMM: C[128x128] = (Ah+Al)[128,K] * Bh[128,K]^T + bias
// hi pass fp32-acc; lo pass fp16-acc (chunk-local, folded per chunk).
// 3-stage cp.async pipeline, 2 CTAs/SM.
// ---------------------------------------------------------------------------
#define BM 128
#define BN 128
#define BK 32
#define LDS 40
#define ARR_HALVES (128 * LDS)             // 5120 halves / plane
#define STAGE_HALVES (3 * ARR_HALVES)      // Ah | Al | Bh
#define NSTAGE 3
#define GEMM_SMEM_BYTES (NSTAGE * STAGE_HALVES * 2)   // 92160

extern __shared__ char dyn_sm[];

__device__ __forceinline__ void gemm_load_stage(
    uint32_t stage, const __half* __restrict__ Ah,
    const __half* __restrict__ Al,
    const __half* __restrict__ Bh, int k0, int tid)
{
#pragma unroll
    for (int t = 0; t < 6; t++) {
        int i   = tid + t * 256;        // 0..1535
        int arr = i >> 9;               // 0..2
        int idx = i & 511;
        int row = idx >> 2;
        int c   = (idx & 3) * 8;
        const __half* g = (arr == 0) ? Ah : (arr == 1) ? Al : Bh;
        uint32_t dst = stage + (uint32_t)(arr * ARR_HALVES + row * LDS + c) * 2;
        cp_async16(dst, g + (size_t)row * DMODEL + k0 + c);
    }
}

// C != nullptr: fp32 store. else: single fp16 plane store to Ch.
__device__ __forceinline__ void gemm_tile_mma(
    const __half* __restrict__ Ah, const __half* __restrict__ Al,
    const __half* __restrict__ Bh,
    const float* __restrict__ bias, float* __restrict__ C,
    __half* __restrict__ Ch, int ldc)
{
    const uint32_t smem_base = smem_u32(dyn_sm);
    const int tid  = threadIdx.x;
    const int wid  = tid >> 5;
    const int lane = tid & 31;
    const int wm   = wid & 3;
    const int wn   = wid >> 2;

    float d[2][8][4];
#pragma unroll
    for (int mt = 0; mt < 2; mt++)
#pragma unroll
        for (int nt = 0; nt < 8; nt++)
#pragma unroll
            for (int j = 0; j < 4; j++) d[mt][nt][j] = 0.0f;

    const int NCH = DMODEL / BK;   // 96

    // prologue: fill stages 0 and 1
    gemm_load_stage(smem_base, Ah, Al, Bh, 0, tid);
    cp_commit();
    gemm_load_stage(smem_base + (uint32_t)(STAGE_HALVES * 2), Ah, Al, Bh, BK, tid);
    cp_commit();

    const int lrow = lane & 15;
    const int lcol = (lane >> 4) * 8;

    int sidx = 0;   // stage of current chunk
    for (int kc = 0; kc < NCH; kc++) {
        if (kc + 2 < NCH) {
            int ls = sidx + 2;
            if (ls >= NSTAGE) ls -= NSTAGE;
            gemm_load_stage(smem_base + (uint32_t)ls * (STAGE_HALVES * 2),
                            Ah, Al, Bh, (kc + 2) * BK, tid);
        }
        cp_commit();
        cp_wait<2>();
        __syncthreads();

        const uint32_t stage = smem_base + (uint32_t)sidx * (STAGE_HALVES * 2);

        // chunk-local fp16 lo accumulator
        uint32_t dlo[2][8][2];
#pragma unroll
        for (int mt = 0; mt < 2; mt++)
#pragma unroll
            for (int nt = 0; nt < 8; nt++) { dlo[mt][nt][0] = 0u; dlo[mt][nt][1] = 0u; }

#pragma unroll
        for (int ks = 0; ks < 2; ks++) {
            uint32_t a_h[2][4], a_l[2][4];
#pragma unroll
            for (int mt = 0; mt < 2; mt++) {
                uint32_t addr = stage +
                    (uint32_t)((wm * 32 + mt * 16 + lrow) * LDS + ks * 16 + lcol) * 2;
                ldsm_x4(a_h[mt], addr);
                ldsm_x4(a_l[mt], addr + ARR_HALVES * 2);
            }
            uint32_t b_h[8][2];
#pragma unroll
            for (int ng = 0; ng < 4; ng++) {
                uint32_t addr = stage + (uint32_t)(2 * ARR_HALVES) * 2 +
                    (uint32_t)((wn * 64 + ng * 16 + lrow) * LDS + ks * 16 + lcol) * 2;
                uint32_t r[4];
                ldsm_x4(r, addr);
                b_h[2 * ng][0] = r[0]; b_h[2 * ng][1] = r[2];
                b_h[2 * ng + 1][0] = r[1]; b_h[2 * ng + 1][1] = r[3];
            }
#pragma unroll
            for (int mt = 0; mt < 2; mt++)
#pragma unroll
                for (int nt = 0; nt < 8; nt++)
                    mma16816(d[mt][nt], a_h[mt], b_h[nt]);
#pragma unroll
            for (int mt = 0; mt < 2; mt++)
#pragma unroll
                for (int nt = 0; nt < 8; nt++)
                    mma16816_h(dlo[mt][nt], a_l[mt], b_h[nt]);
        }
        // fold chunk's lo contribution
#pragma unroll
        for (int mt = 0; mt < 2; mt++)
#pragma unroll
            for (int nt = 0; nt < 8; nt++)
                fold2(d[mt][nt], dlo[mt][nt]);

        __syncthreads();
        if (++sidx == NSTAGE) sidx = 0;
    }

#pragma unroll
    for (int mt = 0; mt < 2; mt++) {
        int r0 = wm * 32 + mt * 16 + (lane >> 2);
#pragma unroll
        for (int nt = 0; nt < 8; nt++) {
            int c0 = wn * 64 + nt * 8 + (lane & 3) * 2;
            float b0 = bias[c0], b1 = bias[c0 + 1];
            float v00 = d[mt][nt][0] + b0, v01 = d[mt][nt][1] + b1;
            float v10 = d[mt][nt][2] + b0, v11 = d[mt][nt][3] + b1;
            if (C != nullptr) {
                *(float2*)&C[(size_t)r0 * ldc + c0]       = make_float2(v00, v01);
                *(float2*)&C[(size_t)(r0 + 8) * ldc + c0] = make_float2(v10, v11);
            } else {
                *(uint32_t*)&Ch[(size_t)r0 * ldc + c0]       = pack2_h(v00, v01);
                *(uint32_t*)&Ch[(size_t)(r0 + 8) * ldc + c0] = pack2_h(v10, v11);
            }
        }
    }
}

__global__ __launch_bounds__(256, 2) void qkv_gemm_kernel(
    const float* __restrict__ bq,  const float* __restrict__ bk,
    const float* __restrict__ bv,  const float* __restrict__ baq,
    const float* __restrict__ bak, const float* __restrict__ bav)
{
    const int n0 = blockIdx.x * BN;
    const int m0 = blockIdx.y * BM;
    const int z  = blockIdx.z;
    const bool txt = (m0 < S_TXT);
    const int widx = txt ? (3 + z) : z;
    const float* bias = (z == 0) ? (txt ? baq : bq)
                      : (z == 1) ? (txt ? bak : bk)
                                 : (txt ? bav : bv);
    const size_t off = (size_t)m0 * DMODEL + n0;
    float* C = (z == 0) ? (g_Q + off) : (z == 1) ? (g_K + off) : nullptr;
    __half* Ch = (z == 2) ? (g_Vh + off) : nullptr;
    const size_t wb = (size_t)widx * DMODEL * DMODEL + (size_t)n0 * DMODEL;
    gemm_tile_mma(g_Xh + (size_t)m0 * DMODEL, g_Xl + (size_t)m0 * DMODEL,
                  g_Wh + wb, bias + n0, C, Ch, DMODEL);
}

__global__ __launch_bounds__(256, 2) void outproj_gemm_kernel(
    const float* __restrict__ b_out, const float* __restrict__ b_add_out,
    float* __restrict__ out)
{
    const int n0 = blockIdx.x * BN;
    const int m0 = blockIdx.y * BM;
    const bool txt = (m0 < S_TXT);
    const int widx = txt ? 7 : 6;
    const float* bias = txt ? b_add_out : b_out;
    float* C = txt ? (out + ((size_t)S_IMG + m0) * DMODEL + n0)
                   : (out + (size_t)(m0 - S_TXT) * DMODEL + n0);
    const size_t wb = (size_t)widx * DMODEL * DMODEL + (size_t)n0 * DMODEL;
    gemm_tile_mma(g_Oh + (size_t)m0 * DMODEL, g_Ol + (size_t)m0 * DMODEL,
                  g_Wh + wb, bias + n0, C, nullptr, DMODEL);
}

// ---------------------------------------------------------------------------
// per-head RMSNorm + RoPE on Q and K -> fp16 hi/lo planes
// ---------------------------------------------------------------------------
__global__ __launch_bounds__(128) void rmsrope_kernel(
    const float* __restrict__ nq,  const float* __restrict__ nk,
    const float* __restrict__ naq, const float* __restrict__ nak,
    const float* __restrict__ img_cos, const float* __restrict__ img_sin,
    const float* __restrict__ txt_cos, const float* __restrict__ txt_sin)
{
    const int sh = blockIdx.x;
    const int s  = sh / NH;
    const int h  = sh - s * NH;
    const int which = blockIdx.y;  // 0 = Q, 1 = K

    const float* buf = which ? g_K : g_Q;
    const float *nw, *ctab, *stab;
    int srow;
    if (s < S_TXT) {
        nw = which ? nak : naq; ctab = txt_cos; stab = txt_sin; srow = s;
    } else {
        nw = which ? nk : nq;   ctab = img_cos; stab = img_sin; srow = s - S_TXT;
    }

    const int d = threadIdx.x;
    const size_t pos = (size_t)s * DMODEL + h * HD + d;
    float v = buf[pos];

    float ss = v * v;
#pragma unroll
    for (int o = 16; o > 0; o >>= 1) ss += __shfl_xor_sync(0xffffffffu, ss, o);
    __shared__ float wsum[4];
    if ((d & 31) == 0) wsum[d >> 5] = ss;
    __syncthreads();
    ss = wsum[0] + wsum[1] + wsum[2] + wsum[3];

    float inv = rsqrtf(ss * (1.0f / HD) + 1e-6f);
    v = v * inv * nw[d];

    float partner = __shfl_xor_sync(0xffffffffu, v, 1);
    float c  = ctab[(size_t)srow * (HD / 2) + (d >> 1)];
    float sn = stab[(size_t)srow * (HD / 2) + (d >> 1)];
    float outv = (d & 1) ? fmaf(partner, sn, v * c) : (v * c - partner * sn);

    __half hi = __float2half_rn(outv);
    __half lo = __float2half_rn(outv - __half2float(hi));
    if (which == 0) { g_Qh[pos] = hi; g_Ql[pos] = lo; }
    else            { g_Kh[pos] = hi; g_Kl[pos] = lo; }
}

// ---------------------------------------------------------------------------
// flash attention on tensor cores
// QK^T: hi fp32-acc + two correction passes fp16-acc; PV: hi fp32 + lo fp16
// ---------------------------------------------------------------------------
#define FQT 128
#define FKT 64
#define FLDS 136
#define FPLANE_Q (FQT * FLDS)
#define FPLANE_K (FKT * FLDS)
#define FQB (FPLANE_Q * 2)
#define FKB (FPLANE_K * 2)
#define FLASH_SMEM (2 * FQB + 6 * FKB)

__device__ __forceinline__ void flash_load_kv(uint32_t dstbase, int k0,
                                              int hoff, int tid)
{
#pragma unroll
    for (int t = 0; t < 12; t++) {
        int i = tid + t * 256;
        int plane = i >> 10;            // 0 Kh, 1 Kl, 2 Vh
        int idx = i & 1023;
        int r = idx >> 4;
        int c = (idx & 15) * 8;
        const __half* g = (plane == 0) ? g_Kh : (plane == 1) ? g_Kl : g_Vh;
        cp_async16(dstbase + (uint32_t)plane * FKB + (uint32_t)(r * FLDS + c) * 2,
                   g + (size_t)(k0 + r) * DMODEL + hoff + c);
    }
}

__global__ __launch_bounds__(256, 1) void flash_mma_kernel()
{
    const uint32_t base = smem_u32(dyn_sm);
    const int tid  = threadIdx.x;
    const int wid  = tid >> 5;
    const int lane = tid & 31;
    const int h    = blockIdx.y;
    const int hoff = h * HD;
    const int q0   = blockIdx.x * FQT;

    const uint32_t sQh = base;
    const uint32_t sKV = base + 2 * FQB;
    const float scale = 0.08838834764831845f;

#pragma unroll
    for (int t = 0; t < 16; t++) {
        int i = tid + t * 256;
        int plane = i >> 11;
        int idx = i & 2047;
        int r = idx >> 4;
        int c = (idx & 15) * 8;
        const __half* g = plane ? g_Ql : g_Qh;
        cp_async16(sQh + (uint32_t)plane * FQB + (uint32_t)(r * FLDS + c) * 2,
                   g + (size_t)(q0 + r) * DMODEL + hoff + c);
    }
    flash_load_kv(sKV, 0, hoff, tid);
    cp_commit();

    float o[16][4];
#pragma unroll
    for (int j = 0; j < 16; j++)
#pragma unroll
        for (int i = 0; i < 4; i++) o[j][i] = 0.0f;
    float m0 = -1e30f, m1 = -1e30f, l0 = 0.0f, l1 = 0.0f;

    const int wq0 = wid * 16;
    const uint32_t lrow  = lane & 15;
    const uint32_t lcolb = (lane >> 4) * 16;

    const int NKT = S_ALL / FKT;   // 44
    for (int kt = 0; kt < NKT; kt++) {
        const uint32_t bufb = sKV + (uint32_t)(kt & 1) * (3 * FKB);
        if (kt + 1 < NKT) {
            flash_load_kv(sKV + (uint32_t)((kt + 1) & 1) * (3 * FKB),
                          (kt + 1) * FKT, hoff, tid);
            cp_commit();
            cp_wait<1>();
        } else {
            cp_wait<0>();
        }
        __syncthreads();

        // ---- S = Q K^T : hi fp32-acc, corrections fp16-acc ----
        float s[8][4];
        uint32_t slo[8][2];
#pragma unroll
        for (int j = 0; j < 8; j++) {
#pragma unroll
            for (int i = 0; i < 4; i++) s[j][i] = 0.0f;
            slo[j][0] = 0u; slo[j][1] = 0u;
        }

#pragma unroll
        for (int ks = 0; ks < 8; ks++) {
            uint32_t qa = sQh + (uint32_t)((wq0 + lrow) * FLDS + ks * 16) * 2 + lcolb;
            uint32_t ah[4], al[4];
            ldsm_x4(ah, qa);
            ldsm_x4(al, qa + FQB);
            uint32_t bh[8][2], bl[8][2];
#pragma unroll
            for (int ng = 0; ng < 4; ng++) {
                uint32_t ka = bufb + (uint32_t)((ng * 16 + lrow) * FLDS + ks * 16) * 2 + lcolb;
                uint32_t rh[4], rl[4];
                ldsm_x4(rh, ka);
                ldsm_x4(rl, ka + FKB);
                bh[2 * ng][0] = rh[0]; bh[2 * ng][1] = rh[2];
                bh[2 * ng + 1][0] = rh[1]; bh[2 * ng + 1][1] = rh[3];
                bl[2 * ng][0] = rl[0]; bl[2 * ng][1] = rl[2];
                bl[2 * ng + 1][0] = rl[1]; bl[2 * ng + 1][1] = rl[3];
            }
#pragma unroll
            for (int j = 0; j < 8; j++) mma16816(s[j], ah, bh[j]);
#pragma unroll
            for (int j = 0; j < 8; j++) mma16816_h(slo[j], ah, bl[j]);
#pragma unroll
            for (int j = 0; j < 8; j++) mma16816_h(slo[j], al, bh[j]);
        }
#pragma unroll
        for (int j = 0; j < 8; j++) fold2(s[j], slo[j]);

        // ---- online softmax (scale applied here) ----
        float mx0 = -1e30f, mx1 = -1e30f;
#pragma unroll
        for (int j = 0; j < 8; j++) {
            mx0 = fmaxf(mx0, fmaxf(s[j][0], s[j][1]));
            mx1 = fmaxf(mx1, fmaxf(s[j][2], s[j][3]));
        }
        mx0 = fmaxf(mx0, __shfl_xor_sync(0xffffffffu, mx0, 1));
        mx0 = fmaxf(mx0, __shfl_xor_sync(0xffffffffu, mx0, 2));
        mx1 = fmaxf(mx1, __shfl_xor_sync(0xffffffffu, mx1, 1));
        mx1 = fmaxf(mx1, __shfl_xor_sync(0xffffffffu, mx1, 2));
        float mn0 = fmaxf(m0, mx0);
        float mn1 = fmaxf(m1, mx1);
        float al0 = __expf((m0 - mn0) * scale);
        float al1 = __expf((m1 - mn1) * scale);
        float rs0 = 0.0f, rs1 = 0.0f;
#pragma unroll
        for (int j = 0; j < 8; j++) {
            s[j][0] = __expf((s[j][0] - mn0) * scale);
            s[j][1] = __expf((s[j][1] - mn0) * scale);
            s[j][2] = __expf((s[j][2] - mn1) * scale);
            s[j][3] = __expf((s[j][3] - mn1) * scale);
            rs0 += s[j][0] + s[j][1];
            rs1 += s[j][2] + s[j][3];
        }
        rs0 += __shfl_xor_sync(0xffffffffu, rs0, 1);
        rs0 += __shfl_xor_sync(0xffffffffu, rs0, 2);
        rs1 += __shfl_xor_sync(0xffffffffu, rs1, 1);
        rs1 += __shfl_xor_sync(0xffffffffu, rs1, 2);
        l0 = l0 * al0 + rs0;
        l1 = l1 * al1 + rs1;
        m0 = mn0;
        m1 = mn1;
#pragma unroll
        for (int j = 0; j < 16; j++) {
            o[j][0] *= al0; o[j][1] *= al0;
            o[j][2] *= al1; o[j][3] *= al1;
        }

        // ---- O += P V : hi fp32-acc, lo fp16-acc ----
        uint32_t olo[16][2];
#pragma unroll
        for (int j = 0; j < 16; j++) { olo[j][0] = 0u; olo[j][1] = 0u; }

        const uint32_t Vb = bufb + 2 * FKB;
#pragma unroll
        for (int t = 0; t < 4; t++) {
            uint32_t aph[4], apl[4];
            split_pack2(s[2 * t][0],     s[2 * t][1],     aph[0], apl[0]);
            split_pack2(s[2 * t][2],     s[2 * t][3],     aph[1], apl[1]);
            split_pack2(s[2 * t + 1][0], s[2 * t + 1][1], aph[2], apl[2]);
            split_pack2(s[2 * t + 1][2], s[2 * t + 1][3], aph[3], apl[3]);
#pragma unroll
            for (int gp = 0; gp < 4; gp++) {
                const int g0 = 2 * gp, g1 = 2 * gp + 1;
                uint32_t va0 = Vb + (uint32_t)((t * 16 + lrow) * FLDS + g0 * 16) * 2 + lcolb;
                uint32_t va1 = Vb + (uint32_t)((t * 16 + lrow) * FLDS + g1 * 16) * 2 + lcolb;
                uint32_t h0[4], h1[4];
                ldsm_x4_t(h0, va0);
                ldsm_x4_t(h1, va1);
                uint32_t bh00[2] = {h0[0], h0[1]}, bh01[2] = {h0[2], h0[3]};
                uint32_t bh10[2] = {h1[0], h1[1]}, bh11[2] = {h1[2], h1[3]};
                mma16816(o[2 * g0],     aph, bh00);
                mma16816(o[2 * g0 + 1], aph, bh01);
                mma16816(o[2 * g1],     aph, bh10);
                mma16816(o[2 * g1 + 1], aph, bh11);
                mma16816_h(olo[2 * g0],     apl, bh00);
                mma16816_h(olo[2 * g0 + 1], apl, bh01);
                mma16816_h(olo[2 * g1],     apl, bh10);
                mma16816_h(olo[2 * g1 + 1], apl, bh11);
            }
        }
#pragma unroll
        for (int j = 0; j < 16; j++) fold2(o[j], olo[j]);
        __syncthreads();
    }

    // ---- epilogue: normalize, split to fp16 hi/lo planes ----
    float il0 = 1.0f / l0, il1 = 1.0f / l1;
    const int r0 = q0 + wq0 + (lane >> 2);
    const int r1 = r0 + 8;
    const int cb = hoff + (lane & 3) * 2;
#pragma unroll
    for (int j = 0; j < 16; j++) {
        int c = cb + j * 8;
        uint32_t hi, lo;
        split_pack2(o[j][0] * il0, o[j][1] * il0, hi, lo);
        *(uint32_t*)&g_Oh[(size_t)r0 * DMODEL + c] = hi;
        *(uint32_t*)&g_Ol[(size_t)r0 * DMODEL + c] = lo;
        split_pack2(o[j][2] * il1, o[j][3] * il1, hi, lo);
        *(uint32_t*)&g_Oh[(size_t)r1 * DMODEL + c] = hi;
        *(uint32_t*)&g_Ol[(size_t)r1 * DMODEL + c] = lo;
    }
}

// ---------------------------------------------------------------------------
extern "C" void kernel_launch(void* const* d_in, const int* in_sizes, int n_in,
                              void* d_out, int out_size)
{
    const float* hid   = (const float*)d_in[0];
    const float* enc   = (const float*)d_in[1];
    const float* wq    = (const float*)d_in[2];
    const float* bq    = (const float*)d_in[3];
    const float* wk    = (const float*)d_in[4];
    const float* bk    = (const float*)d_in[5];
    const float* wv    = (const float*)d_in[6];
    const float* bv    = (const float*)d_in[7];
    const float* waq   = (const float*)d_in[8];
    const float* baq   = (const float*)d_in[9];
    const float* wak   = (const float*)d_in[10];
    const float* bak   = (const float*)d_in[11];
    const float* wav   = (const float*)d_in[12];
    const float* bav   = (const float*)d_in[13];
    const float* nq    = (const float*)d_in[14];
    const float* nk    = (const float*)d_in[15];
    const float* naq   = (const float*)d_in[16];
    const float* nak   = (const float*)d_in[17];
    const float* w_out     = (const float*)d_in[18];
    const float* b_out     = (const float*)d_in[19];
    const float* w_add_out = (const float*)d_in[20];
    const float* b_add_out = (const float*)d_in[21];
    const float* img_cos = (const float*)d_in[22];
    const float* img_sin = (const float*)d_in[23];
    const float* txt_cos = (const float*)d_in[24];
    const float* txt_sin = (const float*)d_in[25];

    float* out = (float*)d_out;

    // prepass conversions
    {
        size_t n4 = (size_t)S_ALL * DMODEL / 4;
        split_x_kernel<<<(unsigned)((n4 + 255) / 256), 256>>>(hid, enc);
        size_t w4 = (size_t)DMODEL * DMODEL / 4;
        dim3 gw((unsigned)((w4 + 255) / 256), 8);
        conv_w_kernel<<<gw, 256>>>(wq, wk, wv, waq, wak, wav, w_out, w_add_out);
    }

    cudaFuncSetAttribute(qkv_gemm_kernel,
                         cudaFuncAttributeMaxDynamicSharedMemorySize,
                         GEMM_SMEM_BYTES);
    qkv_gemm_kernel<<<dim3(DMODEL / BN, S_ALL / BM, 3), 256, GEMM_SMEM_BYTES>>>(
        bq, bk, bv, baq, bak, bav);

    rmsrope_kernel<<<dim3(S_ALL * NH, 2), 128>>>(nq, nk, naq, nak,
                                                 img_cos, img_sin,
                                                 txt_cos, txt_sin);

    cudaFuncSetAttribute(flash_mma_kernel,
                         cudaFuncAttributeMaxDynamicSharedMemorySize,
                         FLASH_SMEM);
    flash_mma_kernel<<<dim3(S_ALL / FQT, NH), 256, FLASH_SMEM>>>();

    cudaFuncSetAttribute(outproj_gemm_kernel,
                         cudaFuncAttributeMaxDynamicSharedMemorySize,
                         GEMM_SMEM_BYTES);
    outproj_gemm_kernel<<<dim3(DMODEL / BN, S_ALL / BM), 256, GEMM_SMEM_BYTES>>>(
        b_out, b_add_out, out);
}

// round 14
// speedup vs baseline: 1.2998x; 1.2998x over previous
#include <cuda_runtime.h>
#include <cuda_fp16.h>
#include <cstdint>
#include <math.h>

// Problem constants
#define S_TXT 512
#define S_IMG 2304
#define S_ALL 2816
#define DMODEL 3072
#define NH 24
#define HD 128

// ---------------------------------------------------------------------------
// Static device scratch (allocation-free rule)
// ---------------------------------------------------------------------------
__device__ float g_Q[S_ALL * DMODEL];
__device__ float g_K[S_ALL * DMODEL];

__device__ __half g_Xh[S_ALL * DMODEL];
__device__ __half g_Xl[S_ALL * DMODEL];
__device__ __half g_Qh[S_ALL * DMODEL];
__device__ __half g_Ql[S_ALL * DMODEL];
__device__ __half g_Kh[S_ALL * DMODEL];
__device__ __half g_Kl[S_ALL * DMODEL];
__device__ __half g_Vh[S_ALL * DMODEL];
__device__ __half g_Oh[S_ALL * DMODEL];
// 8 weight matrices (single fp16 plane): 0=wq 1=wk 2=wv 3=waq 4=wak 5=wav 6=w_out 7=w_add_out
__device__ __half g_Wh[(size_t)8 * DMODEL * DMODEL];

// ---------------------------------------------------------------------------
// helpers
// ---------------------------------------------------------------------------
__device__ __forceinline__ uint32_t smem_u32(const void* p) {
    uint32_t a;
    asm("{ .reg .u64 t; cvta.to.shared.u64 t, %1; cvt.u32.u64 %0, t; }"
        : "=r"(a) : "l"(p));
    return a;
}

__device__ __forceinline__ void cp_async16(uint32_t dst, const void* src) {
    asm volatile("cp.async.cg.shared.global [%0], [%1], 16;"
                 :: "r"(dst), "l"(src));
}
__device__ __forceinline__ void cp_commit() {
    asm volatile("cp.async.commit_group;");
}
template <int N>
__device__ __forceinline__ void cp_wait() {
    asm volatile("cp.async.wait_group %0;" :: "n"(N));
}

__device__ __forceinline__ void ldsm_x4(uint32_t* r, uint32_t addr) {
    asm volatile("ldmatrix.sync.aligned.m8n8.x4.shared.b16 {%0,%1,%2,%3}, [%4];"
                 : "=r"(r[0]), "=r"(r[1]), "=r"(r[2]), "=r"(r[3]) : "r"(addr));
}

__device__ __forceinline__ void ldsm_x4_t(uint32_t* r, uint32_t addr) {
    asm volatile("ldmatrix.sync.aligned.m8n8.x4.trans.shared.b16 {%0,%1,%2,%3}, [%4];"
                 : "=r"(r[0]), "=r"(r[1]), "=r"(r[2]), "=r"(r[3]) : "r"(addr));
}

__device__ __forceinline__ void mma16816(float* d, const uint32_t* a,
                                         const uint32_t* b) {
    asm volatile(
        "mma.sync.aligned.m16n8k16.row.col.f32.f16.f16.f32 "
        "{%0,%1,%2,%3}, {%4,%5,%6,%7}, {%8,%9}, {%0,%1,%2,%3};"
        : "+f"(d[0]), "+f"(d[1]), "+f"(d[2]), "+f"(d[3])
        : "r"(a[0]), "r"(a[1]), "r"(a[2]), "r"(a[3]), "r"(b[0]), "r"(b[1]));
}

// fp16 hi/lo split of a pair of fp32 values, packed as __half2 words
__device__ __forceinline__ void split_pack2(float f0, float f1,
                                            uint32_t& hi, uint32_t& lo)
{
    __half h0 = __float2half_rn(f0);
    __half h1 = __float2half_rn(f1);
    __half l0 = __float2half_rn(f0 - __half2float(h0));
    __half l1 = __float2half_rn(f1 - __half2float(h1));
    __half2 H = {h0, h1}, L = {l0, l1};
    hi = *(uint32_t*)&H;
    lo = *(uint32_t*)&L;
}

__device__ __forceinline__ uint32_t pack2_h(float f0, float f1)
{
    __half2 H = {__float2half_rn(f0), __float2half_rn(f1)};
    return *(uint32_t*)&H;
}

// ---------------------------------------------------------------------------
// prepass: fp32 -> fp16 hi/lo (X) and fp32 -> fp16 (W)
// ---------------------------------------------------------------------------
__device__ __forceinline__ void split_store4(
    float4 v, __half* hi, __half* lo)
{
    uint32_t h0, h1, l0, l1;
    split_pack2(v.x, v.y, h0, l0);
    split_pack2(v.z, v.w, h1, l1);
    uint2 Hv = {h0, h1}, Lv = {l0, l1};
    *(uint2*)hi = Hv;
    *(uint2*)lo = Lv;
}

__global__ __launch_bounds__(256) void split_x_kernel(
    const float* __restrict__ hid, const float* __restrict__ enc)
{
    size_t i = (size_t)blockIdx.x * blockDim.x + threadIdx.x;
    size_t n4 = (size_t)S_ALL * DMODEL / 4;
    if (i >= n4) return;
    size_t e = i * 4;
    size_t row = e / DMODEL;
    const float* src = (row < S_TXT) ? (enc + e)
                                     : (hid + (e - (size_t)S_TXT * DMODEL));
    split_store4(*(const float4*)src, g_Xh + e, g_Xl + e);
}

__global__ __launch_bounds__(256) void conv_w_kernel(
    const float* __restrict__ w0, const float* __restrict__ w1,
    const float* __restrict__ w2, const float* __restrict__ w3,
    const float* __restrict__ w4, const float* __restrict__ w5,
    const float* __restrict__ w6, const float* __restrict__ w7)
{
    const float* ws[8] = {w0, w1, w2, w3, w4, w5, w6, w7};
    int widx = blockIdx.y;
    size_t i = (size_t)blockIdx.x * blockDim.x + threadIdx.x;
    size_t n4 = (size_t)DMODEL * DMODEL / 4;
    if (i >= n4) return;
    size_t e = i * 4;
    float4 v = *(const float4*)(ws[widx] + e);
    uint2 H = {pack2_h(v.x, v.y), pack2_h(v.z, v.w)};
    *(uint2*)&g_Wh[(size_t)widx * DMODEL * DMODEL + e] = H;
}

// ---------------------------------------------------------------------------
// mma.sync fp16 GEMM: C[128x128] = (Ah[+Al])[128,K] * Bh[128,K]^T + bias
// has_lo selects 2-pass (A hi+lo) or 1-pass (A hi only). fp32 accumulate.
// 3-stage cp.async pipeline, 2 CTAs/SM.
// ---------------------------------------------------------------------------
#define BM 128
#define BN 128
#define BK 32
#define LDS 40
#define ARR_HALVES (128 * LDS)             // 5120 halves / plane
#define STAGE_HALVES (3 * ARR_HALVES)      // Ah | Al | Bh
#define NSTAGE 3
#define GEMM_SMEM_BYTES (NSTAGE * STAGE_HALVES * 2)   // 92160

extern __shared__ char dyn_sm[];

__device__ __forceinline__ void gemm_load_stage(
    uint32_t stage, const __half* __restrict__ Ah,
    const __half* __restrict__ Al,
    const __half* __restrict__ Bh, int k0, int tid, bool has_lo)
{
#pragma unroll
    for (int t = 0; t < 6; t++) {
        int i   = tid + t * 256;        // 0..1535
        int arr = i >> 9;               // 0..2
        if (arr == 1 && !has_lo) continue;
        int idx = i & 511;
        int row = idx >> 2;
        int c   = (idx & 3) * 8;
        const __half* g = (arr == 0) ? Ah : (arr == 1) ? Al : Bh;
        uint32_t dst = stage + (uint32_t)(arr * ARR_HALVES + row * LDS + c) * 2;
        cp_async16(dst, g + (size_t)row * DMODEL + k0 + c);
    }
}

// C != nullptr: fp32 store. else: single fp16 plane store to Ch.
__device__ __forceinline__ void gemm_tile_mma(
    const __half* __restrict__ Ah, const __half* __restrict__ Al,
    const __half* __restrict__ Bh,
    const float* __restrict__ bias, float* __restrict__ C,
    __half* __restrict__ Ch, int ldc, bool has_lo)
{
    const uint32_t smem_base = smem_u32(dyn_sm);
    const int tid  = threadIdx.x;
    const int wid  = tid >> 5;
    const int lane = tid & 31;
    const int wm   = wid & 3;
    const int wn   = wid >> 2;

    float d[2][8][4];
#pragma unroll
    for (int mt = 0; mt < 2; mt++)
#pragma unroll
        for (int nt = 0; nt < 8; nt++)
#pragma unroll
            for (int j = 0; j < 4; j++) d[mt][nt][j] = 0.0f;

    const int NCH = DMODEL / BK;   // 96

    // prologue: fill stages 0 and 1
    gemm_load_stage(smem_base, Ah, Al, Bh, 0, tid, has_lo);
    cp_commit();
    gemm_load_stage(smem_base + (uint32_t)(STAGE_HALVES * 2), Ah, Al, Bh, BK,
                    tid, has_lo);
    cp_commit();

    const int lrow = lane & 15;
    const int lcol = (lane >> 4) * 8;

    int sidx = 0;   // stage of current chunk
    for (int kc = 0; kc < NCH; kc++) {
        if (kc + 2 < NCH) {
            int ls = sidx + 2;
            if (ls >= NSTAGE) ls -= NSTAGE;
            gemm_load_stage(smem_base + (uint32_t)ls * (STAGE_HALVES * 2),
                            Ah, Al, Bh, (kc + 2) * BK, tid, has_lo);
        }
        cp_commit();
        cp_wait<2>();
        __syncthreads();

        const uint32_t stage = smem_base + (uint32_t)sidx * (STAGE_HALVES * 2);

#pragma unroll
        for (int ks = 0; ks < 2; ks++) {
            uint32_t a_h[2][4], a_l[2][4];
#pragma unroll
            for (int mt = 0; mt < 2; mt++) {
                uint32_t addr = stage +
                    (uint32_t)((wm * 32 + mt * 16 + lrow) * LDS + ks * 16 + lcol) * 2;
                ldsm_x4(a_h[mt], addr);
                if (has_lo) ldsm_x4(a_l[mt], addr + ARR_HALVES * 2);
            }
            uint32_t b_h[8][2];
#pragma unroll
            for (int ng = 0; ng < 4; ng++) {
                uint32_t addr = stage + (uint32_t)(2 * ARR_HALVES) * 2 +
                    (uint32_t)((wn * 64 + ng * 16 + lrow) * LDS + ks * 16 + lcol) * 2;
                uint32_t r[4];
                ldsm_x4(r, addr);
                b_h[2 * ng][0] = r[0]; b_h[2 * ng][1] = r[2];
                b_h[2 * ng + 1][0] = r[1]; b_h[2 * ng + 1][1] = r[3];
            }
#pragma unroll
            for (int mt = 0; mt < 2; mt++)
#pragma unroll
                for (int nt = 0; nt < 8; nt++)
                    mma16816(d[mt][nt], a_h[mt], b_h[nt]);
            if (has_lo) {
#pragma unroll
                for (int mt = 0; mt < 2; mt++)
#pragma unroll
                    for (int nt = 0; nt < 8; nt++)
                        mma16816(d[mt][nt], a_l[mt], b_h[nt]);
            }
        }
        __syncthreads();
        if (++sidx == NSTAGE) sidx = 0;
    }

#pragma unroll
    for (int mt = 0; mt < 2; mt++) {
        int r0 = wm * 32 + mt * 16 + (lane >> 2);
#pragma unroll
        for (int nt = 0; nt < 8; nt++) {
            int c0 = wn * 64 + nt * 8 + (lane & 3) * 2;
            float b0 = bias[c0], b1 = bias[c0 + 1];
            float v00 = d[mt][nt][0] + b0, v01 = d[mt][nt][1] + b1;
            float v10 = d[mt][nt][2] + b0, v11 = d[mt][nt][3] + b1;
            if (C != nullptr) {
                *(float2*)&C[(size_t)r0 * ldc + c0]       = make_float2(v00, v01);
                *(float2*)&C[(size_t)(r0 + 8) * ldc + c0] = make_float2(v10, v11);
            } else {
                *(uint32_t*)&Ch[(size_t)r0 * ldc + c0]       = pack2_h(v00, v01);
                *(uint32_t*)&Ch[(size_t)(r0 + 8) * ldc + c0] = pack2_h(v10, v11);
            }
        }
    }
}

__global__ __launch_bounds__(256, 2) void qkv_gemm_kernel(
    const float* __restrict__ bq,  const float* __restrict__ bk,
    const float* __restrict__ bv,  const float* __restrict__ baq,
    const float* __restrict__ bak, const float* __restrict__ bav)
{
    const int n0 = blockIdx.x * BN;
    const int m0 = blockIdx.y * BM;
    const int z  = blockIdx.z;
    const bool txt = (m0 < S_TXT);
    const int widx = txt ? (3 + z) : z;
    const float* bias = (z == 0) ? (txt ? baq : bq)
                      : (z == 1) ? (txt ? bak : bk)
                                 : (txt ? bav : bv);
    const size_t off = (size_t)m0 * DMODEL + n0;
    float* C = (z == 0) ? (g_Q + off) : (z == 1) ? (g_K + off) : nullptr;
    __half* Ch = (z == 2) ? (g_Vh + off) : nullptr;
    const size_t wb = (size_t)widx * DMODEL * DMODEL + (size_t)n0 * DMODEL;
    // V projection (z==2): 1-pass — V is stored fp16 anyway; Q/K: 2-pass
    gemm_tile_mma(g_Xh + (size_t)m0 * DMODEL, g_Xl + (size_t)m0 * DMODEL,
                  g_Wh + wb, bias + n0, C, Ch, DMODEL, z != 2);
}

__global__ __launch_bounds__(256, 2) void outproj_gemm_kernel(
    const float* __restrict__ b_out, const float* __restrict__ b_add_out,
    float* __restrict__ out)
{
    const int n0 = blockIdx.x * BN;
    const int m0 = blockIdx.y * BM;
    const bool txt = (m0 < S_TXT);
    const int widx = txt ? 7 : 6;
    const float* bias = txt ? b_add_out : b_out;
    float* C = txt ? (out + ((size_t)S_IMG + m0) * DMODEL + n0)
                   : (out + (size_t)(m0 - S_TXT) * DMODEL + n0);
    const size_t wb = (size_t)widx * DMODEL * DMODEL + (size_t)n0 * DMODEL;
    // 1-pass: O stored as single fp16 plane
    gemm_tile_mma(g_Oh + (size_t)m0 * DMODEL, nullptr,
                  g_Wh + wb, bias + n0, C, nullptr, DMODEL, false);
}

// ---------------------------------------------------------------------------
// per-head RMSNorm + RoPE on Q and K -> fp16 hi/lo planes
// ---------------------------------------------------------------------------
__global__ __launch_bounds__(128) void rmsrope_kernel(
    const float* __restrict__ nq,  const float* __restrict__ nk,
    const float* __restrict__ naq, const float* __restrict__ nak,
    const float* __restrict__ img_cos, const float* __restrict__ img_sin,
    const float* __restrict__ txt_cos, const float* __restrict__ txt_sin)
{
    const int sh = blockIdx.x;
    const int s  = sh / NH;
    const int h  = sh - s * NH;
    const int which = blockIdx.y;  // 0 = Q, 1 = K

    const float* buf = which ? g_K : g_Q;
    const float *nw, *ctab, *stab;
    int srow;
    if (s < S_TXT) {
        nw = which ? nak : naq; ctab = txt_cos; stab = txt_sin; srow = s;
    } else {
        nw = which ? nk : nq;   ctab = img_cos; stab = img_sin; srow = s - S_TXT;
    }

    const int d = threadIdx.x;
    const size_t pos = (size_t)s * DMODEL + h * HD + d;
    float v = buf[pos];

    float ss = v * v;
#pragma unroll
    for (int o = 16; o > 0; o >>= 1) ss += __shfl_xor_sync(0xffffffffu, ss, o);
    __shared__ float wsum[4];
    if ((d & 31) == 0) wsum[d >> 5] = ss;
    __syncthreads();
    ss = wsum[0] + wsum[1] + wsum[2] + wsum[3];

    float inv = rsqrtf(ss * (1.0f / HD) + 1e-6f);
    v = v * inv * nw[d];

    float partner = __shfl_xor_sync(0xffffffffu, v, 1);
    float c  = ctab[(size_t)srow * (HD / 2) + (d >> 1)];
    float sn = stab[(size_t)srow * (HD / 2) + (d >> 1)];
    float outv = (d & 1) ? fmaf(partner, sn, v * c) : (v * c - partner * sn);

    __half hi = __float2half_rn(outv);
    __half lo = __float2half_rn(outv - __half2float(hi));
    if (which == 0) { g_Qh[pos] = hi; g_Ql[pos] = lo; }
    else            { g_Kh[pos] = hi; g_Kl[pos] = lo; }
}

// ---------------------------------------------------------------------------
// flash attention on tensor cores (R10 config: QK 3-pass fp32-acc,
// PV 2-pass fp32-acc). Epilogue writes single fp16 plane g_Oh.
// ---------------------------------------------------------------------------
#define FQT 128
#define FKT 64
#define FLDS 136
#define FPLANE_Q (FQT * FLDS)
#define FPLANE_K (FKT * FLDS)
#define FQB (FPLANE_Q * 2)
#define FKB (FPLANE_K * 2)
#define FLASH_SMEM (2 * FQB + 6 * FKB)

__device__ __forceinline__ void flash_load_kv(uint32_t dstbase, int k0,
                                              int hoff, int tid)
{
#pragma unroll
    for (int t = 0; t < 12; t++) {
        int i = tid + t * 256;
        int plane = i >> 10;            // 0 Kh, 1 Kl, 2 Vh
        int idx = i & 1023;
        int r = idx >> 4;
        int c = (idx & 15) * 8;
        const __half* g = (plane == 0) ? g_Kh : (plane == 1) ? g_Kl : g_Vh;
        cp_async16(dstbase + (uint32_t)plane * FKB + (uint32_t)(r * FLDS + c) * 2,
                   g + (size_t)(k0 + r) * DMODEL + hoff + c);
    }
}

__global__ __launch_bounds__(256, 1) void flash_mma_kernel()
{
    const uint32_t base = smem_u32(dyn_sm);
    const int tid  = threadIdx.x;
    const int wid  = tid >> 5;
    const int lane = tid & 31;
    const int h    = blockIdx.y;
    const int hoff = h * HD;
    const int q0   = blockIdx.x * FQT;

    const uint32_t sQh = base;
    const uint32_t sKV = base + 2 * FQB;
    const float scale = 0.08838834764831845f;

#pragma unroll
    for (int t = 0; t < 16; t++) {
        int i = tid + t * 256;
        int plane = i >> 11;
        int idx = i & 2047;
        int r = idx >> 4;
        int c = (idx & 15) * 8;
        const __half* g = plane ? g_Ql : g_Qh;
        cp_async16(sQh + (uint32_t)plane * FQB + (uint32_t)(r * FLDS + c) * 2,
                   g + (size_t)(q0 + r) * DMODEL + hoff + c);
    }
    flash_load_kv(sKV, 0, hoff, tid);
    cp_commit();

    float o[16][4];
#pragma unroll
    for (int j = 0; j < 16; j++)
#pragma unroll
        for (int i = 0; i < 4; i++) o[j][i] = 0.0f;
    float m0 = -1e30f, m1 = -1e30f, l0 = 0.0f, l1 = 0.0f;

    const int wq0 = wid * 16;
    const uint32_t lrow  = lane & 15;
    const uint32_t lcolb = (lane >> 4) * 16;

    const int NKT = S_ALL / FKT;   // 44
    for (int kt = 0; kt < NKT; kt++) {
        const uint32_t bufb = sKV + (uint32_t)(kt & 1) * (3 * FKB);
        if (kt + 1 < NKT) {
            flash_load_kv(sKV + (uint32_t)((kt + 1) & 1) * (3 * FKB),
                          (kt + 1) * FKT, hoff, tid);
            cp_commit();
            cp_wait<1>();
        } else {
            cp_wait<0>();
        }
        __syncthreads();

        // ---- S = Q K^T (3-pass split fp16, fp32-acc) ----
        float s[8][4];
#pragma unroll
        for (int j = 0; j < 8; j++)
#pragma unroll
            for (int i = 0; i < 4; i++) s[j][i] = 0.0f;

#pragma unroll
        for (int ks = 0; ks < 8; ks++) {
            uint32_t qa = sQh + (uint32_t)((wq0 + lrow) * FLDS + ks * 16) * 2 + lcolb;
            uint32_t ah[4], al[4];
            ldsm_x4(ah, qa);
            ldsm_x4(al, qa + FQB);
            uint32_t bh[8][2], bl[8][2];
#pragma unroll
            for (int ng = 0; ng < 4; ng++) {
                uint32_t ka = bufb + (uint32_t)((ng * 16 + lrow) * FLDS + ks * 16) * 2 + lcolb;
                uint32_t rh[4], rl[4];
                ldsm_x4(rh, ka);
                ldsm_x4(rl, ka + FKB);
                bh[2 * ng][0] = rh[0]; bh[2 * ng][1] = rh[2];
                bh[2 * ng + 1][0] = rh[1]; bh[2 * ng + 1][1] = rh[3];
                bl[2 * ng][0] = rl[0]; bl[2 * ng][1] = rl[2];
                bl[2 * ng + 1][0] = rl[1]; bl[2 * ng + 1][1] = rl[3];
            }
#pragma unroll
            for (int j = 0; j < 8; j++) mma16816(s[j], ah, bh[j]);
#pragma unroll
            for (int j = 0; j < 8; j++) mma16816(s[j], ah, bl[j]);
#pragma unroll
            for (int j = 0; j < 8; j++) mma16816(s[j], al, bh[j]);
        }

        // ---- online softmax (scale applied here) ----
        float mx0 = -1e30f, mx1 = -1e30f;
#pragma unroll
        for (int j = 0; j < 8; j++) {
            mx0 = fmaxf(mx0, fmaxf(s[j][0], s[j][1]));
            mx1 = fmaxf(mx1, fmaxf(s[j][2], s[j][3]));
        }
        mx0 = fmaxf(mx0, __shfl_xor_sync(0xffffffffu, mx0, 1));
        mx0 = fmaxf(mx0, __shfl_xor_sync(0xffffffffu, mx0, 2));
        mx1 = fmaxf(mx1, __shfl_xor_sync(0xffffffffu, mx1, 1));
        mx1 = fmaxf(mx1, __shfl_xor_sync(0xffffffffu, mx1, 2));
        float mn0 = fmaxf(m0, mx0);
        float mn1 = fmaxf(m1, mx1);
        float al0 = __expf((m0 - mn0) * scale);
        float al1 = __expf((m1 - mn1) * scale);
        float rs0 = 0.0f, rs1 = 0.0f;
#pragma unroll
        for (int j = 0; j < 8; j++) {
            s[j][0] = __expf((s[j][0] - mn0) * scale);
            s[j][1] = __expf((s[j][1] - mn0) * scale);
            s[j][2] = __expf((s[j][2] - mn1) * scale);
            s[j][3] = __expf((s[j][3] - mn1) * scale);
            rs0 += s[j][0] + s[j][1];
            rs1 += s[j][2] + s[j][3];
        }
        rs0 += __shfl_xor_sync(0xffffffffu, rs0, 1);
        rs0 += __shfl_xor_sync(0xffffffffu, rs0, 2);
        rs1 += __shfl_xor_sync(0xffffffffu, rs1, 1);
        rs1 += __shfl_xor_sync(0xffffffffu, rs1, 2);
        l0 = l0 * al0 + rs0;
        l1 = l1 * al1 + rs1;
        m0 = mn0;
        m1 = mn1;
#pragma unroll
        for (int j = 0; j < 16; j++) {
            o[j][0] *= al0; o[j][1] *= al0;
            o[j][2] *= al1; o[j][3] *= al1;
        }

        // ---- O += P V (2-pass: P split fp16, V single; fp32-acc) ----
        const uint32_t Vb = bufb + 2 * FKB;
#pragma unroll
        for (int t = 0; t < 4; t++) {
            uint32_t aph[4], apl[4];
            split_pack2(s[2 * t][0],     s[2 * t][1],     aph[0], apl[0]);
            split_pack2(s[2 * t][2],     s[2 * t][3],     aph[1], apl[1]);
            split_pack2(s[2 * t + 1][0], s[2 * t + 1][1], aph[2], apl[2]);
            split_pack2(s[2 * t + 1][2], s[2 * t + 1][3], aph[3], apl[3]);
#pragma unroll
            for (int gp = 0; gp < 4; gp++) {
                const int g0 = 2 * gp, g1 = 2 * gp + 1;
                uint32_t va0 = Vb + (uint32_t)((t * 16 + lrow) * FLDS + g0 * 16) * 2 + lcolb;
                uint32_t va1 = Vb + (uint32_t)((t * 16 + lrow) * FLDS + g1 * 16) * 2 + lcolb;
                uint32_t h0[4], h1[4];
                ldsm_x4_t(h0, va0);
                ldsm_x4_t(h1, va1);
                uint32_t bh00[2] = {h0[0], h0[1]}, bh01[2] = {h0[2], h0[3]};
                uint32_t bh10[2] = {h1[0], h1[1]}, bh11[2] = {h1[2], h1[3]};
                mma16816(o[2 * g0],     aph, bh00);
                mma16816(o[2 * g0 + 1], aph, bh01);
                mma16816(o[2 * g1],     aph, bh10);
                mma16816(o[2 * g1 + 1], aph, bh11);
                mma16816(o[2 * g0],     apl, bh00);
                mma16816(o[2 * g0 + 1], apl, bh01);
                mma16816(o[2 * g1],     apl, bh10);
                mma16816(o[2 * g1 + 1], apl, bh11);
            }
        }
        __syncthreads();
    }

    // ---- epilogue: normalize, store single fp16 plane ----
    float il0 = 1.0f / l0, il1 = 1.0f / l1;
    const int r0 = q0 + wq0 + (lane >> 2);
    const int r1 = r0 + 8;
    const int cb = hoff + (lane & 3) * 2;
#pragma unroll
    for (int j = 0; j < 16; j++) {
        int c = cb + j * 8;
        *(uint32_t*)&g_Oh[(size_t)r0 * DMODEL + c] =
            pack2_h(o[j][0] * il0, o[j][1] * il0);
        *(uint32_t*)&g_Oh[(size_t)r1 * DMODEL + c] =
            pack2_h(o[j][2] * il1, o[j][3] * il1);
    }
}

// ---------------------------------------------------------------------------
extern "C" void kernel_launch(void* const* d_in, const int* in_sizes, int n_in,
                              void* d_out, int out_size)
{
    const float* hid   = (const float*)d_in[0];
    const float* enc   = (const float*)d_in[1];
    const float* wq    = (const float*)d_in[2];
    const float* bq    = (const float*)d_in[3];
    const float* wk    = (const float*)d_in[4];
    const float* bk    = (const float*)d_in[5];
    const float* wv    = (const float*)d_in[6];
    const float* bv    = (const float*)d_in[7];
    const float* waq   = (const float*)d_in[8];
    const float* baq   = (const float*)d_in[9];
    const float* wak   = (const float*)d_in[10];
    const float* bak   = (const float*)d_in[11];
    const float* wav   = (const float*)d_in[12];
    const float* bav   = (const float*)d_in[13];
    const float* nq    = (const float*)d_in[14];
    const float* nk    = (const float*)d_in[15];
    const float* naq   = (const float*)d_in[16];
    const float* nak   = (const float*)d_in[17];
    const float* w_out     = (const float*)d_in[18];
    const float* b_out     = (const float*)d_in[19];
    const float* w_add_out = (const float*)d_in[20];
    const float* b_add_out = (const float*)d_in[21];
    const float* img_cos = (const float*)d_in[22];
    const float* img_sin = (const float*)d_in[23];
    const float* txt_cos = (const float*)d_in[24];
    const float* txt_sin = (const float*)d_in[25];

    float* out = (float*)d_out;

    // prepass conversions
    {
        size_t n4 = (size_t)S_ALL * DMODEL / 4;
        split_x_kernel<<<(unsigned)((n4 + 255) / 256), 256>>>(hid, enc);
        size_t w4 = (size_t)DMODEL * DMODEL / 4;
        dim3 gw((unsigned)((w4 + 255) / 256), 8);
        conv_w_kernel<<<gw, 256>>>(wq, wk, wv, waq, wak, wav, w_out, w_add_out);
    }

    cudaFuncSetAttribute(qkv_gemm_kernel,
                         cudaFuncAttributeMaxDynamicSharedMemorySize,
                         GEMM_SMEM_BYTES);
    qkv_gemm_kernel<<<dim3(DMODEL / BN, S_ALL / BM, 3), 256, GEMM_SMEM_BYTES>>>(
        bq, bk, bv, baq, bak, bav);

    rmsrope_kernel<<<dim3(S_ALL * NH, 2), 128>>>(nq, nk, naq, nak,
                                                 img_cos, img_sin,
                                                 txt_cos, txt_sin);

    cudaFuncSetAttribute(flash_mma_kernel,
                         cudaFuncAttributeMaxDynamicSharedMemorySize,
                         FLASH_SMEM);
    flash_mma_kernel<<<dim3(S_ALL / FQT, NH), 256, FLASH_SMEM>>>();

    cudaFuncSetAttribute(outproj_gemm_kernel,
                         cudaFuncAttributeMaxDynamicSharedMemorySize,
                         GEMM_SMEM_BYTES);
    outproj_gemm_kernel<<<dim3(DMODEL / BN, S_ALL / BM), 256, GEMM_SMEM_BYTES>>>(
        b_out, b_add_out, out);
}

// round 15
// speedup vs baseline: 1.5517x; 1.1938x over previous
#include <cuda_runtime.h>
#include <cuda_fp16.h>
#include <cstdint>
#include <math.h>

// Problem constants
#define S_TXT 512
#define S_IMG 2304
#define S_ALL 2816
#define DMODEL 3072
#define NH 24
#define HD 128

// ---------------------------------------------------------------------------
// Static device scratch (allocation-free rule)
// ---------------------------------------------------------------------------
__device__ float g_Q[S_ALL * DMODEL];
__device__ float g_K[S_ALL * DMODEL];

__device__ __half g_Xh[S_ALL * DMODEL];
__device__ __half g_Qh[S_ALL * DMODEL];
__device__ __half g_Ql[S_ALL * DMODEL];
__device__ __half g_Kh[S_ALL * DMODEL];
__device__ __half g_Kl[S_ALL * DMODEL];
__device__ __half g_Vh[S_ALL * DMODEL];
__device__ __half g_Oh[S_ALL * DMODEL];
// 8 weight matrices (single fp16 plane): 0=wq 1=wk 2=wv 3=waq 4=wak 5=wav 6=w_out 7=w_add_out
__device__ __half g_Wh[(size_t)8 * DMODEL * DMODEL];

// ---------------------------------------------------------------------------
// helpers
// ---------------------------------------------------------------------------
__device__ __forceinline__ uint32_t smem_u32(const void* p) {
    uint32_t a;
    asm("{ .reg .u64 t; cvta.to.shared.u64 t, %1; cvt.u32.u64 %0, t; }"
        : "=r"(a) : "l"(p));
    return a;
}

__device__ __forceinline__ void cp_async16(uint32_t dst, const void* src) {
    asm volatile("cp.async.cg.shared.global [%0], [%1], 16;"
                 :: "r"(dst), "l"(src));
}
__device__ __forceinline__ void cp_commit() {
    asm volatile("cp.async.commit_group;");
}
template <int N>
__device__ __forceinline__ void cp_wait() {
    asm volatile("cp.async.wait_group %0;" :: "n"(N));
}

__device__ __forceinline__ void ldsm_x4(uint32_t* r, uint32_t addr) {
    asm volatile("ldmatrix.sync.aligned.m8n8.x4.shared.b16 {%0,%1,%2,%3}, [%4];"
                 : "=r"(r[0]), "=r"(r[1]), "=r"(r[2]), "=r"(r[3]) : "r"(addr));
}

__device__ __forceinline__ void ldsm_x4_t(uint32_t* r, uint32_t addr) {
    asm volatile("ldmatrix.sync.aligned.m8n8.x4.trans.shared.b16 {%0,%1,%2,%3}, [%4];"
                 : "=r"(r[0]), "=r"(r[1]), "=r"(r[2]), "=r"(r[3]) : "r"(addr));
}

__device__ __forceinline__ void mma16816(float* d, const uint32_t* a,
                                         const uint32_t* b) {
    asm volatile(
        "mma.sync.aligned.m16n8k16.row.col.f32.f16.f16.f32 "
        "{%0,%1,%2,%3}, {%4,%5,%6,%7}, {%8,%9}, {%0,%1,%2,%3};"
        : "+f"(d[0]), "+f"(d[1]), "+f"(d[2]), "+f"(d[3])
        : "r"(a[0]), "r"(a[1]), "r"(a[2]), "r"(a[3]), "r"(b[0]), "r"(b[1]));
}

// fp16 hi/lo split of a pair of fp32 values, packed as __half2 words
__device__ __forceinline__ void split_pack2(float f0, float f1,
                                            uint32_t& hi, uint32_t& lo)
{
    __half h0 = __float2half_rn(f0);
    __half h1 = __float2half_rn(f1);
    __half l0 = __float2half_rn(f0 - __half2float(h0));
    __half l1 = __float2half_rn(f1 - __half2float(h1));
    __half2 H = {h0, h1}, L = {l0, l1};
    hi = *(uint32_t*)&H;
    lo = *(uint32_t*)&L;
}

__device__ __forceinline__ uint32_t pack2_h(float f0, float f1)
{
    __half2 H = {__float2half_rn(f0), __float2half_rn(f1)};
    return *(uint32_t*)&H;
}

// ---------------------------------------------------------------------------
// prepass: fp32 -> fp16 for X and W
// ---------------------------------------------------------------------------
__global__ __launch_bounds__(256) void conv_x_kernel(
    const float* __restrict__ hid, const float* __restrict__ enc)
{
    size_t i = (size_t)blockIdx.x * blockDim.x + threadIdx.x;
    size_t n4 = (size_t)S_ALL * DMODEL / 4;
    if (i >= n4) return;
    size_t e = i * 4;
    size_t row = e / DMODEL;
    const float* src = (row < S_TXT) ? (enc + e)
                                     : (hid + (e - (size_t)S_TXT * DMODEL));
    float4 v = *(const float4*)src;
    uint2 H = {pack2_h(v.x, v.y), pack2_h(v.z, v.w)};
    *(uint2*)&g_Xh[e] = H;
}

__global__ __launch_bounds__(256) void conv_w_kernel(
    const float* __restrict__ w0, const float* __restrict__ w1,
    const float* __restrict__ w2, const float* __restrict__ w3,
    const float* __restrict__ w4, const float* __restrict__ w5,
    const float* __restrict__ w6, const float* __restrict__ w7)
{
    const float* ws[8] = {w0, w1, w2, w3, w4, w5, w6, w7};
    int widx = blockIdx.y;
    size_t i = (size_t)blockIdx.x * blockDim.x + threadIdx.x;
    size_t n4 = (size_t)DMODEL * DMODEL / 4;
    if (i >= n4) return;
    size_t e = i * 4;
    float4 v = *(const float4*)(ws[widx] + e);
    uint2 H = {pack2_h(v.x, v.y), pack2_h(v.z, v.w)};
    *(uint2*)&g_Wh[(size_t)widx * DMODEL * DMODEL + e] = H;
}

// ---------------------------------------------------------------------------
// mma.sync 1-pass fp16 GEMM: C[128x128] = Ah[128,K] * Bh[128,K]^T + bias
// fp32 accumulate. 3-stage cp.async pipeline, 2 CTAs/SM.
// ---------------------------------------------------------------------------
#define BM 128
#define BN 128
#define BK 32
#define LDS 40
#define ARR_HALVES (128 * LDS)             // 5120 halves / plane
#define STAGE_HALVES (2 * ARR_HALVES)      // Ah | Bh
#define NSTAGE 3
#define GEMM_SMEM_BYTES (NSTAGE * STAGE_HALVES * 2)   // 61440

extern __shared__ char dyn_sm[];

__device__ __forceinline__ void gemm_load_stage(
    uint32_t stage, const __half* __restrict__ Ah,
    const __half* __restrict__ Bh, int k0, int tid)
{
#pragma unroll
    for (int t = 0; t < 4; t++) {
        int i   = tid + t * 256;        // 0..1023
        int arr = i >> 9;               // 0..1
        int idx = i & 511;
        int row = idx >> 2;
        int c   = (idx & 3) * 8;
        const __half* g = (arr == 0) ? Ah : Bh;
        uint32_t dst = stage + (uint32_t)(arr * ARR_HALVES + row * LDS + c) * 2;
        cp_async16(dst, g + (size_t)row * DMODEL + k0 + c);
    }
}

// C != nullptr: fp32 store. else: single fp16 plane store to Ch.
__device__ __forceinline__ void gemm_tile_mma(
    const __half* __restrict__ Ah, const __half* __restrict__ Bh,
    const float* __restrict__ bias, float* __restrict__ C,
    __half* __restrict__ Ch, int ldc)
{
    const uint32_t smem_base = smem_u32(dyn_sm);
    const int tid  = threadIdx.x;
    const int wid  = tid >> 5;
    const int lane = tid & 31;
    const int wm   = wid & 3;
    const int wn   = wid >> 2;

    float d[2][8][4];
#pragma unroll
    for (int mt = 0; mt < 2; mt++)
#pragma unroll
        for (int nt = 0; nt < 8; nt++)
#pragma unroll
            for (int j = 0; j < 4; j++) d[mt][nt][j] = 0.0f;

    const int NCH = DMODEL / BK;   // 96

    gemm_load_stage(smem_base, Ah, Bh, 0, tid);
    cp_commit();
    gemm_load_stage(smem_base + (uint32_t)(STAGE_HALVES * 2), Ah, Bh, BK, tid);
    cp_commit();

    const int lrow = lane & 15;
    const int lcol = (lane >> 4) * 8;

    int sidx = 0;
    for (int kc = 0; kc < NCH; kc++) {
        if (kc + 2 < NCH) {
            int ls = sidx + 2;
            if (ls >= NSTAGE) ls -= NSTAGE;
            gemm_load_stage(smem_base + (uint32_t)ls * (STAGE_HALVES * 2),
                            Ah, Bh, (kc + 2) * BK, tid);
        }
        cp_commit();
        cp_wait<2>();
        __syncthreads();

        const uint32_t stage = smem_base + (uint32_t)sidx * (STAGE_HALVES * 2);

#pragma unroll
        for (int ks = 0; ks < 2; ks++) {
            uint32_t a_h[2][4];
#pragma unroll
            for (int mt = 0; mt < 2; mt++) {
                uint32_t addr = stage +
                    (uint32_t)((wm * 32 + mt * 16 + lrow) * LDS + ks * 16 + lcol) * 2;
                ldsm_x4(a_h[mt], addr);
            }
            uint32_t b_h[8][2];
#pragma unroll
            for (int ng = 0; ng < 4; ng++) {
                uint32_t addr = stage + (uint32_t)ARR_HALVES * 2 +
                    (uint32_t)((wn * 64 + ng * 16 + lrow) * LDS + ks * 16 + lcol) * 2;
                uint32_t r[4];
                ldsm_x4(r, addr);
                b_h[2 * ng][0] = r[0]; b_h[2 * ng][1] = r[2];
                b_h[2 * ng + 1][0] = r[1]; b_h[2 * ng + 1][1] = r[3];
            }
#pragma unroll
            for (int mt = 0; mt < 2; mt++)
#pragma unroll
                for (int nt = 0; nt < 8; nt++)
                    mma16816(d[mt][nt], a_h[mt], b_h[nt]);
        }
        __syncthreads();
        if (++sidx == NSTAGE) sidx = 0;
    }

#pragma unroll
    for (int mt = 0; mt < 2; mt++) {
        int r0 = wm * 32 + mt * 16 + (lane >> 2);
#pragma unroll
        for (int nt = 0; nt < 8; nt++) {
            int c0 = wn * 64 + nt * 8 + (lane & 3) * 2;
            float b0 = bias[c0], b1 = bias[c0 + 1];
            float v00 = d[mt][nt][0] + b0, v01 = d[mt][nt][1] + b1;
            float v10 = d[mt][nt][2] + b0, v11 = d[mt][nt][3] + b1;
            if (C != nullptr) {
                *(float2*)&C[(size_t)r0 * ldc + c0]       = make_float2(v00, v01);
                *(float2*)&C[(size_t)(r0 + 8) * ldc + c0] = make_float2(v10, v11);
            } else {
                *(uint32_t*)&Ch[(size_t)r0 * ldc + c0]       = pack2_h(v00, v01);
                *(uint32_t*)&Ch[(size_t)(r0 + 8) * ldc + c0] = pack2_h(v10, v11);
            }
        }
    }
}

__global__ __launch_bounds__(256, 2) void qkv_gemm_kernel(
    const float* __restrict__ bq,  const float* __restrict__ bk,
    const float* __restrict__ bv,  const float* __restrict__ baq,
    const float* __restrict__ bak, const float* __restrict__ bav)
{
    const int n0 = blockIdx.x * BN;
    const int m0 = blockIdx.y * BM;
    const int z  = blockIdx.z;
    const bool txt = (m0 < S_TXT);
    const int widx = txt ? (3 + z) : z;
    const float* bias = (z == 0) ? (txt ? baq : bq)
                      : (z == 1) ? (txt ? bak : bk)
                                 : (txt ? bav : bv);
    const size_t off = (size_t)m0 * DMODEL + n0;
    float* C = (z == 0) ? (g_Q + off) : (z == 1) ? (g_K + off) : nullptr;
    __half* Ch = (z == 2) ? (g_Vh + off) : nullptr;
    const size_t wb = (size_t)widx * DMODEL * DMODEL + (size_t)n0 * DMODEL;
    gemm_tile_mma(g_Xh + (size_t)m0 * DMODEL, g_Wh + wb, bias + n0, C, Ch, DMODEL);
}

__global__ __launch_bounds__(256, 2) void outproj_gemm_kernel(
    const float* __restrict__ b_out, const float* __restrict__ b_add_out,
    float* __restrict__ out)
{
    const int n0 = blockIdx.x * BN;
    const int m0 = blockIdx.y * BM;
    const bool txt = (m0 < S_TXT);
    const int widx = txt ? 7 : 6;
    const float* bias = txt ? b_add_out : b_out;
    float* C = txt ? (out + ((size_t)S_IMG + m0) * DMODEL + n0)
                   : (out + (size_t)(m0 - S_TXT) * DMODEL + n0);
    const size_t wb = (size_t)widx * DMODEL * DMODEL + (size_t)n0 * DMODEL;
    gemm_tile_mma(g_Oh + (size_t)m0 * DMODEL, g_Wh + wb, bias + n0, C, nullptr, DMODEL);
}

// ---------------------------------------------------------------------------
// per-head RMSNorm + RoPE, warp-per-head: 256 threads = 8 warps = 8 items.
// Each lane owns 4 consecutive dims (float4); RoPE pairs are intra-lane.
// ---------------------------------------------------------------------------
__global__ __launch_bounds__(256) void rmsrope_kernel(
    const float* __restrict__ nq,  const float* __restrict__ nk,
    const float* __restrict__ naq, const float* __restrict__ nak,
    const float* __restrict__ img_cos, const float* __restrict__ img_sin,
    const float* __restrict__ txt_cos, const float* __restrict__ txt_sin)
{
    const int item = blockIdx.x * 8 + (threadIdx.x >> 5);
    const int lane = threadIdx.x & 31;
    const int which = (item >= S_ALL * NH) ? 1 : 0;   // 0 = Q, 1 = K
    const int sh = which ? (item - S_ALL * NH) : item;
    const int s  = sh / NH;
    const int h  = sh - s * NH;

    const float* buf = which ? g_K : g_Q;
    const float *nw, *ctab, *stab;
    int srow;
    if (s < S_TXT) {
        nw = which ? nak : naq; ctab = txt_cos; stab = txt_sin; srow = s;
    } else {
        nw = which ? nk : nq;   ctab = img_cos; stab = img_sin; srow = s - S_TXT;
    }

    const size_t pos = (size_t)s * DMODEL + h * HD + lane * 4;
    float4 v = *(const float4*)&buf[pos];

    float ss = v.x * v.x + v.y * v.y + v.z * v.z + v.w * v.w;
#pragma unroll
    for (int o = 16; o > 0; o >>= 1) ss += __shfl_xor_sync(0xffffffffu, ss, o);

    float inv = rsqrtf(ss * (1.0f / HD) + 1e-6f);
    float4 nwv = *(const float4*)&nw[lane * 4];
    v.x *= inv * nwv.x;
    v.y *= inv * nwv.y;
    v.z *= inv * nwv.z;
    v.w *= inv * nwv.w;

    float2 cs = *(const float2*)&ctab[(size_t)srow * (HD / 2) + lane * 2];
    float2 sn = *(const float2*)&stab[(size_t)srow * (HD / 2) + lane * 2];
    float o0 = v.x * cs.x - v.y * sn.x;
    float o1 = v.x * sn.x + v.y * cs.x;
    float o2 = v.z * cs.y - v.w * sn.y;
    float o3 = v.z * sn.y + v.w * cs.y;

    uint32_t h0, l0, h1, l1;
    split_pack2(o0, o1, h0, l0);
    split_pack2(o2, o3, h1, l1);
    uint2 H = {h0, h1}, L = {l0, l1};
    if (which == 0) {
        *(uint2*)&g_Qh[pos] = H;
        *(uint2*)&g_Ql[pos] = L;
    } else {
        *(uint2*)&g_Kh[pos] = H;
        *(uint2*)&g_Kl[pos] = L;
    }
}

// ---------------------------------------------------------------------------
// flash attention on tensor cores (unchanged): QK 3-pass fp32-acc,
// PV 2-pass fp32-acc. Epilogue writes single fp16 plane g_Oh.
// ---------------------------------------------------------------------------
#define FQT 128
#define FKT 64
#define FLDS 136
#define FPLANE_Q (FQT * FLDS)
#define FPLANE_K (FKT * FLDS)
#define FQB (FPLANE_Q * 2)
#define FKB (FPLANE_K * 2)
#define FLASH_SMEM (2 * FQB + 6 * FKB)

__device__ __forceinline__ void flash_load_kv(uint32_t dstbase, int k0,
                                              int hoff, int tid)
{
#pragma unroll
    for (int t = 0; t < 12; t++) {
        int i = tid + t * 256;
        int plane = i >> 10;            // 0 Kh, 1 Kl, 2 Vh
        int idx = i & 1023;
        int r = idx >> 4;
        int c = (idx & 15) * 8;
        const __half* g = (plane == 0) ? g_Kh : (plane == 1) ? g_Kl : g_Vh;
        cp_async16(dstbase + (uint32_t)plane * FKB + (uint32_t)(r * FLDS + c) * 2,
                   g + (size_t)(k0 + r) * DMODEL + hoff + c);
    }
}

__global__ __launch_bounds__(256, 1) void flash_mma_kernel()
{
    const uint32_t base = smem_u32(dyn_sm);
    const int tid  = threadIdx.x;
    const int wid  = tid >> 5;
    const int lane = tid & 31;
    const int h    = blockIdx.y;
    const int hoff = h * HD;
    const int q0   = blockIdx.x * FQT;

    const uint32_t sQh = base;
    const uint32_t sKV = base + 2 * FQB;
    const float scale = 0.08838834764831845f;

#pragma unroll
    for (int t = 0; t < 16; t++) {
        int i = tid + t * 256;
        int plane = i >> 11;
        int idx = i & 2047;
        int r = idx >> 4;
        int c = (idx & 15) * 8;
        const __half* g = plane ? g_Ql : g_Qh;
        cp_async16(sQh + (uint32_t)plane * FQB + (uint32_t)(r * FLDS + c) * 2,
                   g + (size_t)(q0 + r) * DMODEL + hoff + c);
    }
    flash_load_kv(sKV, 0, hoff, tid);
    cp_commit();

    float o[16][4];
#pragma unroll
    for (int j = 0; j < 16; j++)
#pragma unroll
        for (int i = 0; i < 4; i++) o[j][i] = 0.0f;
    float m0 = -1e30f, m1 = -1e30f, l0 = 0.0f, l1 = 0.0f;

    const int wq0 = wid * 16;
    const uint32_t lrow  = lane & 15;
    const uint32_t lcolb = (lane >> 4) * 16;

    const int NKT = S_ALL / FKT;   // 44
    for (int kt = 0; kt < NKT; kt++) {
        const uint32_t bufb = sKV + (uint32_t)(kt & 1) * (3 * FKB);
        if (kt + 1 < NKT) {
            flash_load_kv(sKV + (uint32_t)((kt + 1) & 1) * (3 * FKB),
                          (kt + 1) * FKT, hoff, tid);
            cp_commit();
            cp_wait<1>();
        } else {
            cp_wait<0>();
        }
        __syncthreads();

        // ---- S = Q K^T (3-pass split fp16, fp32-acc) ----
        float s[8][4];
#pragma unroll
        for (int j = 0; j < 8; j++)
#pragma unroll
            for (int i = 0; i < 4; i++) s[j][i] = 0.0f;

#pragma unroll
        for (int ks = 0; ks < 8; ks++) {
            uint32_t qa = sQh + (uint32_t)((wq0 + lrow) * FLDS + ks * 16) * 2 + lcolb;
            uint32_t ah[4], al[4];
            ldsm_x4(ah, qa);
            ldsm_x4(al, qa + FQB);
            uint32_t bh[8][2], bl[8][2];
#pragma unroll
            for (int ng = 0; ng < 4; ng++) {
                uint32_t ka = bufb + (uint32_t)((ng * 16 + lrow) * FLDS + ks * 16) * 2 + lcolb;
                uint32_t rh[4], rl[4];
                ldsm_x4(rh, ka);
                ldsm_x4(rl, ka + FKB);
                bh[2 * ng][0] = rh[0]; bh[2 * ng][1] = rh[2];
                bh[2 * ng + 1][0] = rh[1]; bh[2 * ng + 1][1] = rh[3];
                bl[2 * ng][0] = rl[0]; bl[2 * ng][1] = rl[2];
                bl[2 * ng + 1][0] = rl[1]; bl[2 * ng + 1][1] = rl[3];
            }
#pragma unroll
            for (int j = 0; j < 8; j++) mma16816(s[j], ah, bh[j]);
#pragma unroll
            for (int j = 0; j < 8; j++) mma16816(s[j], ah, bl[j]);
#pragma unroll
            for (int j = 0; j < 8; j++) mma16816(s[j], al, bh[j]);
        }

        // ---- online softmax (scale applied here) ----
        float mx0 = -1e30f, mx1 = -1e30f;
#pragma unroll
        for (int j = 0; j < 8; j++) {
            mx0 = fmaxf(mx0, fmaxf(s[j][0], s[j][1]));
            mx1 = fmaxf(mx1, fmaxf(s[j][2], s[j][3]));
        }
        mx0 = fmaxf(mx0, __shfl_xor_sync(0xffffffffu, mx0, 1));
        mx0 = fmaxf(mx0, __shfl_xor_sync(0xffffffffu, mx0, 2));
        mx1 = fmaxf(mx1, __shfl_xor_sync(0xffffffffu, mx1, 1));
        mx1 = fmaxf(mx1, __shfl_xor_sync(0xffffffffu, mx1, 2));
        float mn0 = fmaxf(m0, mx0);
        float mn1 = fmaxf(m1, mx1);
        float al0 = __expf((m0 - mn0) * scale);
        float al1 = __expf((m1 - mn1) * scale);
        float rs0 = 0.0f, rs1 = 0.0f;
#pragma unroll
        for (int j = 0; j < 8; j++) {
            s[j][0] = __expf((s[j][0] - mn0) * scale);
            s[j][1] = __expf((s[j][1] - mn0) * scale);
            s[j][2] = __expf((s[j][2] - mn1) * scale);
            s[j][3] = __expf((s[j][3] - mn1) * scale);
            rs0 += s[j][0] + s[j][1];
            rs1 += s[j][2] + s[j][3];
        }
        rs0 += __shfl_xor_sync(0xffffffffu, rs0, 1);
        rs0 += __shfl_xor_sync(0xffffffffu, rs0, 2);
        rs1 += __shfl_xor_sync(0xffffffffu, rs1, 1);
        rs1 += __shfl_xor_sync(0xffffffffu, rs1, 2);
        l0 = l0 * al0 + rs0;
        l1 = l1 * al1 + rs1;
        m0 = mn0;
        m1 = mn1;
#pragma unroll
        for (int j = 0; j < 16; j++) {
            o[j][0] *= al0; o[j][1] *= al0;
            o[j][2] *= al1; o[j][3] *= al1;
        }

        // ---- O += P V (2-pass: P split fp16, V single; fp32-acc) ----
        const uint32_t Vb = bufb + 2 * FKB;
#pragma unroll
        for (int t = 0; t < 4; t++) {
            uint32_t aph[4], apl[4];
            split_pack2(s[2 * t][0],     s[2 * t][1],     aph[0], apl[0]);
            split_pack2(s[2 * t][2],     s[2 * t][3],     aph[1], apl[1]);
            split_pack2(s[2 * t + 1][0], s[2 * t + 1][1], aph[2], apl[2]);
            split_pack2(s[2 * t + 1][2], s[2 * t + 1][3], aph[3], apl[3]);
#pragma unroll
            for (int gp = 0; gp < 4; gp++) {
                const int g0 = 2 * gp, g1 = 2 * gp + 1;
                uint32_t va0 = Vb + (uint32_t)((t * 16 + lrow) * FLDS + g0 * 16) * 2 + lcolb;
                uint32_t va1 = Vb + (uint32_t)((t * 16 + lrow) * FLDS + g1 * 16) * 2 + lcolb;
                uint32_t h0[4], h1[4];
                ldsm_x4_t(h0, va0);
                ldsm_x4_t(h1, va1);
                uint32_t bh00[2] = {h0[0], h0[1]}, bh01[2] = {h0[2], h0[3]};
                uint32_t bh10[2] = {h1[0], h1[1]}, bh11[2] = {h1[2], h1[3]};
                mma16816(o[2 * g0],     aph, bh00);
                mma16816(o[2 * g0 + 1], aph, bh01);
                mma16816(o[2 * g1],     aph, bh10);
                mma16816(o[2 * g1 + 1], aph, bh11);
                mma16816(o[2 * g0],     apl, bh00);
                mma16816(o[2 * g0 + 1], apl, bh01);
                mma16816(o[2 * g1],     apl, bh10);
                mma16816(o[2 * g1 + 1], apl, bh11);
            }
        }
        __syncthreads();
    }

    // ---- epilogue: normalize, store single fp16 plane ----
    float il0 = 1.0f / l0, il1 = 1.0f / l1;
    const int r0 = q0 + wq0 + (lane >> 2);
    const int r1 = r0 + 8;
    const int cb = hoff + (lane & 3) * 2;
#pragma unroll
    for (int j = 0; j < 16; j++) {
        int c = cb + j * 8;
        *(uint32_t*)&g_Oh[(size_t)r0 * DMODEL + c] =
            pack2_h(o[j][0] * il0, o[j][1] * il0);
        *(uint32_t*)&g_Oh[(size_t)r1 * DMODEL + c] =
            pack2_h(o[j][2] * il1, o[j][3] * il1);
    }
}

// ---------------------------------------------------------------------------
extern "C" void kernel_launch(void* const* d_in, const int* in_sizes, int n_in,
                              void* d_out, int out_size)
{
    const float* hid   = (const float*)d_in[0];
    const float* enc   = (const float*)d_in[1];
    const float* wq    = (const float*)d_in[2];
    const float* bq    = (const float*)d_in[3];
    const float* wk    = (const float*)d_in[4];
    const float* bk    = (const float*)d_in[5];
    const float* wv    = (const float*)d_in[6];
    const float* bv    = (const float*)d_in[7];
    const float* waq   = (const float*)d_in[8];
    const float* baq   = (const float*)d_in[9];
    const float* wak   = (const float*)d_in[10];
    const float* bak   = (const float*)d_in[11];
    const float* wav   = (const float*)d_in[12];
    const float* bav   = (const float*)d_in[13];
    const float* nq    = (const float*)d_in[14];
    const float* nk    = (const float*)d_in[15];
    const float* naq   = (const float*)d_in[16];
    const float* nak   = (const float*)d_in[17];
    const float* w_out     = (const float*)d_in[18];
    const float* b_out     = (const float*)d_in[19];
    const float* w_add_out = (const float*)d_in[20];
    const float* b_add_out = (const float*)d_in[21];
    const float* img_cos = (const float*)d_in[22];
    const float* img_sin = (const float*)d_in[23];
    const float* txt_cos = (const float*)d_in[24];
    const float* txt_sin = (const float*)d_in[25];

    float* out = (float*)d_out;

    // prepass conversions
    {
        size_t n4 = (size_t)S_ALL * DMODEL / 4;
        conv_x_kernel<<<(unsigned)((n4 + 255) / 256), 256>>>(hid, enc);
        size_t w4 = (size_t)DMODEL * DMODEL / 4;
        dim3 gw((unsigned)((w4 + 255) / 256), 8);
        conv_w_kernel<<<gw, 256>>>(wq, wk, wv, waq, wak, wav, w_out, w_add_out);
    }

    cudaFuncSetAttribute(qkv_gemm_kernel,
                         cudaFuncAttributeMaxDynamicSharedMemorySize,
                         GEMM_SMEM_BYTES);
    qkv_gemm_kernel<<<dim3(DMODEL / BN, S_ALL / BM, 3), 256, GEMM_SMEM_BYTES>>>(
        bq, bk, bv, baq, bak, bav);

    rmsrope_kernel<<<(S_ALL * NH * 2) / 8, 256>>>(nq, nk, naq, nak,
                                                  img_cos, img_sin,
                                                  txt_cos, txt_sin);

    cudaFuncSetAttribute(flash_mma_kernel,
                         cudaFuncAttributeMaxDynamicSharedMemorySize,
                         FLASH_SMEM);
    flash_mma_kernel<<<dim3(S_ALL / FQT, NH), 256, FLASH_SMEM>>>();

    cudaFuncSetAttribute(outproj_gemm_kernel,
                         cudaFuncAttributeMaxDynamicSharedMemorySize,
                         GEMM_SMEM_BYTES);
    outproj_gemm_kernel<<<dim3(DMODEL / BN, S_ALL / BM), 256, GEMM_SMEM_BYTES>>>(
        b_out, b_add_out, out);
}

// round 16
// speedup vs baseline: 1.8029x; 1.1619x over previous
#include <cuda_runtime.h>
#include <cuda_fp16.h>
#include <cstdint>
#include <math.h>

// Problem constants
#define S_TXT 512
#define S_IMG 2304
#define S_ALL 2816
#define DMODEL 3072
#define NH 24
#define HD 128

// ---------------------------------------------------------------------------
// Static device scratch (allocation-free rule)
// ---------------------------------------------------------------------------
__device__ float g_Q[S_ALL * DMODEL];
__device__ float g_K[S_ALL * DMODEL];

__device__ __half g_Xh[S_ALL * DMODEL];
__device__ __half g_Qh[S_ALL * DMODEL];
__device__ __half g_Ql[S_ALL * DMODEL];
__device__ __half g_Kh[S_ALL * DMODEL];
__device__ __half g_Vh[S_ALL * DMODEL];
__device__ __half g_Oh[S_ALL * DMODEL];
// 8 weight matrices (single fp16 plane): 0=wq 1=wk 2=wv 3=waq 4=wak 5=wav 6=w_out 7=w_add_out
__device__ __half g_Wh[(size_t)8 * DMODEL * DMODEL];

// ---------------------------------------------------------------------------
// helpers
// ---------------------------------------------------------------------------
__device__ __forceinline__ uint32_t smem_u32(const void* p) {
    uint32_t a;
    asm("{ .reg .u64 t; cvta.to.shared.u64 t, %1; cvt.u32.u64 %0, t; }"
        : "=r"(a) : "l"(p));
    return a;
}

__device__ __forceinline__ void cp_async16(uint32_t dst, const void* src) {
    asm volatile("cp.async.cg.shared.global [%0], [%1], 16;"
                 :: "r"(dst), "l"(src));
}
__device__ __forceinline__ void cp_commit() {
    asm volatile("cp.async.commit_group;");
}
template <int N>
__device__ __forceinline__ void cp_wait() {
    asm volatile("cp.async.wait_group %0;" :: "n"(N));
}

__device__ __forceinline__ void ldsm_x4(uint32_t* r, uint32_t addr) {
    asm volatile("ldmatrix.sync.aligned.m8n8.x4.shared.b16 {%0,%1,%2,%3}, [%4];"
                 : "=r"(r[0]), "=r"(r[1]), "=r"(r[2]), "=r"(r[3]) : "r"(addr));
}

__device__ __forceinline__ void ldsm_x4_t(uint32_t* r, uint32_t addr) {
    asm volatile("ldmatrix.sync.aligned.m8n8.x4.trans.shared.b16 {%0,%1,%2,%3}, [%4];"
                 : "=r"(r[0]), "=r"(r[1]), "=r"(r[2]), "=r"(r[3]) : "r"(addr));
}

__device__ __forceinline__ void mma16816(float* d, const uint32_t* a,
                                         const uint32_t* b) {
    asm volatile(
        "mma.sync.aligned.m16n8k16.row.col.f32.f16.f16.f32 "
        "{%0,%1,%2,%3}, {%4,%5,%6,%7}, {%8,%9}, {%0,%1,%2,%3};"
        : "+f"(d[0]), "+f"(d[1]), "+f"(d[2]), "+f"(d[3])
        : "r"(a[0]), "r"(a[1]), "r"(a[2]), "r"(a[3]), "r"(b[0]), "r"(b[1]));
}

// fp16 hi/lo split of a pair of fp32 values, packed as __half2 words
__device__ __forceinline__ void split_pack2(float f0, float f1,
                                            uint32_t& hi, uint32_t& lo)
{
    __half h0 = __float2half_rn(f0);
    __half h1 = __float2half_rn(f1);
    __half l0 = __float2half_rn(f0 - __half2float(h0));
    __half l1 = __float2half_rn(f1 - __half2float(h1));
    __half2 H = {h0, h1}, L = {l0, l1};
    hi = *(uint32_t*)&H;
    lo = *(uint32_t*)&L;
}

__device__ __forceinline__ uint32_t pack2_h(float f0, float f1)
{
    __half2 H = {__float2half_rn(f0), __float2half_rn(f1)};
    return *(uint32_t*)&H;
}

// ---------------------------------------------------------------------------
// prepass: fp32 -> fp16 for X and W
// ---------------------------------------------------------------------------
__global__ __launch_bounds__(256) void conv_x_kernel(
    const float* __restrict__ hid, const float* __restrict__ enc)
{
    size_t i = (size_t)blockIdx.x * blockDim.x + threadIdx.x;
    size_t n4 = (size_t)S_ALL * DMODEL / 4;
    if (i >= n4) return;
    size_t e = i * 4;
    size_t row = e / DMODEL;
    const float* src = (row < S_TXT) ? (enc + e)
                                     : (hid + (e - (size_t)S_TXT * DMODEL));
    float4 v = *(const float4*)src;
    uint2 H = {pack2_h(v.x, v.y), pack2_h(v.z, v.w)};
    *(uint2*)&g_Xh[e] = H;
}

__global__ __launch_bounds__(256) void conv_w_kernel(
    const float* __restrict__ w0, const float* __restrict__ w1,
    const float* __restrict__ w2, const float* __restrict__ w3,
    const float* __restrict__ w4, const float* __restrict__ w5,
    const float* __restrict__ w6, const float* __restrict__ w7)
{
    const float* ws[8] = {w0, w1, w2, w3, w4, w5, w6, w7};
    int widx = blockIdx.y;
    size_t i = (size_t)blockIdx.x * blockDim.x + threadIdx.x;
    size_t n4 = (size_t)DMODEL * DMODEL / 4;
    if (i >= n4) return;
    size_t e = i * 4;
    float4 v = *(const float4*)(ws[widx] + e);
    uint2 H = {pack2_h(v.x, v.y), pack2_h(v.z, v.w)};
    *(uint2*)&g_Wh[(size_t)widx * DMODEL * DMODEL + e] = H;
}

// ---------------------------------------------------------------------------
// mma.sync 1-pass fp16 GEMM: C[128x128] = Ah[128,K] * Bh[128,K]^T + bias
// fp32 accumulate. 3-stage cp.async pipeline, 2 CTAs/SM.
// ---------------------------------------------------------------------------
#define BM 128
#define BN 128
#define BK 32
#define LDS 40
#define ARR_HALVES (128 * LDS)             // 5120 halves / plane
#define STAGE_HALVES (2 * ARR_HALVES)      // Ah | Bh
#define NSTAGE 3
#define GEMM_SMEM_BYTES (NSTAGE * STAGE_HALVES * 2)   // 61440

extern __shared__ char dyn_sm[];

__device__ __forceinline__ void gemm_load_stage(
    uint32_t stage, const __half* __restrict__ Ah,
    const __half* __restrict__ Bh, int k0, int tid)
{
#pragma unroll
    for (int t = 0; t < 4; t++) {
        int i   = tid + t * 256;        // 0..1023
        int arr = i >> 9;               // 0..1
        int idx = i & 511;
        int row = idx >> 2;
        int c   = (idx & 3) * 8;
        const __half* g = (arr == 0) ? Ah : Bh;
        uint32_t dst = stage + (uint32_t)(arr * ARR_HALVES + row * LDS + c) * 2;
        cp_async16(dst, g + (size_t)row * DMODEL + k0 + c);
    }
}

// C != nullptr: fp32 store. else: single fp16 plane store to Ch.
__device__ __forceinline__ void gemm_tile_mma(
    const __half* __restrict__ Ah, const __half* __restrict__ Bh,
    const float* __restrict__ bias, float* __restrict__ C,
    __half* __restrict__ Ch, int ldc)
{
    const uint32_t smem_base = smem_u32(dyn_sm);
    const int tid  = threadIdx.x;
    const int wid  = tid >> 5;
    const int lane = tid & 31;
    const int wm   = wid & 3;
    const int wn   = wid >> 2;

    float d[2][8][4];
#pragma unroll
    for (int mt = 0; mt < 2; mt++)
#pragma unroll
        for (int nt = 0; nt < 8; nt++)
#pragma unroll
            for (int j = 0; j < 4; j++) d[mt][nt][j] = 0.0f;

    const int NCH = DMODEL / BK;   // 96

    gemm_load_stage(smem_base, Ah, Bh, 0, tid);
    cp_commit();
    gemm_load_stage(smem_base + (uint32_t)(STAGE_HALVES * 2), Ah, Bh, BK, tid);
    cp_commit();

    const int lrow = lane & 15;
    const int lcol = (lane >> 4) * 8;

    int sidx = 0;
    for (int kc = 0; kc < NCH; kc++) {
        if (kc + 2 < NCH) {
            int ls = sidx + 2;
            if (ls >= NSTAGE) ls -= NSTAGE;
            gemm_load_stage(smem_base + (uint32_t)ls * (STAGE_HALVES * 2),
                            Ah, Bh, (kc + 2) * BK, tid);
        }
        cp_commit();
        cp_wait<2>();
        __syncthreads();

        const uint32_t stage = smem_base + (uint32_t)sidx * (STAGE_HALVES * 2);

#pragma unroll
        for (int ks = 0; ks < 2; ks++) {
            uint32_t a_h[2][4];
#pragma unroll
            for (int mt = 0; mt < 2; mt++) {
                uint32_t addr = stage +
                    (uint32_t)((wm * 32 + mt * 16 + lrow) * LDS + ks * 16 + lcol) * 2;
                ldsm_x4(a_h[mt], addr);
            }
            uint32_t b_h[8][2];
#pragma unroll
            for (int ng = 0; ng < 4; ng++) {
                uint32_t addr = stage + (uint32_t)ARR_HALVES * 2 +
                    (uint32_t)((wn * 64 + ng * 16 + lrow) * LDS + ks * 16 + lcol) * 2;
                uint32_t r[4];
                ldsm_x4(r, addr);
                b_h[2 * ng][0] = r[0]; b_h[2 * ng][1] = r[2];
                b_h[2 * ng + 1][0] = r[1]; b_h[2 * ng + 1][1] = r[3];
            }
#pragma unroll
            for (int mt = 0; mt < 2; mt++)
#pragma unroll
                for (int nt = 0; nt < 8; nt++)
                    mma16816(d[mt][nt], a_h[mt], b_h[nt]);
        }
        __syncthreads();
        if (++sidx == NSTAGE) sidx = 0;
    }

#pragma unroll
    for (int mt = 0; mt < 2; mt++) {
        int r0 = wm * 32 + mt * 16 + (lane >> 2);
#pragma unroll
        for (int nt = 0; nt < 8; nt++) {
            int c0 = wn * 64 + nt * 8 + (lane & 3) * 2;
            float b0 = bias[c0], b1 = bias[c0 + 1];
            float v00 = d[mt][nt][0] + b0, v01 = d[mt][nt][1] + b1;
            float v10 = d[mt][nt][2] + b0, v11 = d[mt][nt][3] + b1;
            if (C != nullptr) {
                *(float2*)&C[(size_t)r0 * ldc + c0]       = make_float2(v00, v01);
                *(float2*)&C[(size_t)(r0 + 8) * ldc + c0] = make_float2(v10, v11);
            } else {
                *(uint32_t*)&Ch[(size_t)r0 * ldc + c0]       = pack2_h(v00, v01);
                *(uint32_t*)&Ch[(size_t)(r0 + 8) * ldc + c0] = pack2_h(v10, v11);
            }
        }
    }
}

__global__ __launch_bounds__(256, 2) void qkv_gemm_kernel(
    const float* __restrict__ bq,  const float* __restrict__ bk,
    const float* __restrict__ bv,  const float* __restrict__ baq,
    const float* __restrict__ bak, const float* __restrict__ bav)
{
    const int n0 = blockIdx.x * BN;
    const int m0 = blockIdx.y * BM;
    const int z  = blockIdx.z;
    const bool txt = (m0 < S_TXT);
    const int widx = txt ? (3 + z) : z;
    const float* bias = (z == 0) ? (txt ? baq : bq)
                      : (z == 1) ? (txt ? bak : bk)
                                 : (txt ? bav : bv);
    const size_t off = (size_t)m0 * DMODEL + n0;
    float* C = (z == 0) ? (g_Q + off) : (z == 1) ? (g_K + off) : nullptr;
    __half* Ch = (z == 2) ? (g_Vh + off) : nullptr;
    const size_t wb = (size_t)widx * DMODEL * DMODEL + (size_t)n0 * DMODEL;
    gemm_tile_mma(g_Xh + (size_t)m0 * DMODEL, g_Wh + wb, bias + n0, C, Ch, DMODEL);
}

__global__ __launch_bounds__(256, 2) void outproj_gemm_kernel(
    const float* __restrict__ b_out, const float* __restrict__ b_add_out,
    float* __restrict__ out)
{
    const int n0 = blockIdx.x * BN;
    const int m0 = blockIdx.y * BM;
    const bool txt = (m0 < S_TXT);
    const int widx = txt ? 7 : 6;
    const float* bias = txt ? b_add_out : b_out;
    float* C = txt ? (out + ((size_t)S_IMG + m0) * DMODEL + n0)
                   : (out + (size_t)(m0 - S_TXT) * DMODEL + n0);
    const size_t wb = (size_t)widx * DMODEL * DMODEL + (size_t)n0 * DMODEL;
    gemm_tile_mma(g_Oh + (size_t)m0 * DMODEL, g_Wh + wb, bias + n0, C, nullptr, DMODEL);
}

// ---------------------------------------------------------------------------
// per-head RMSNorm + RoPE, warp-per-head.
// Q -> hi/lo split planes; K -> single fp16 plane.
// ---------------------------------------------------------------------------
__global__ __launch_bounds__(256) void rmsrope_kernel(
    const float* __restrict__ nq,  const float* __restrict__ nk,
    const float* __restrict__ naq, const float* __restrict__ nak,
    const float* __restrict__ img_cos, const float* __restrict__ img_sin,
    const float* __restrict__ txt_cos, const float* __restrict__ txt_sin)
{
    const int item = blockIdx.x * 8 + (threadIdx.x >> 5);
    const int lane = threadIdx.x & 31;
    const int which = (item >= S_ALL * NH) ? 1 : 0;   // 0 = Q, 1 = K
    const int sh = which ? (item - S_ALL * NH) : item;
    const int s  = sh / NH;
    const int h  = sh - s * NH;

    const float* buf = which ? g_K : g_Q;
    const float *nw, *ctab, *stab;
    int srow;
    if (s < S_TXT) {
        nw = which ? nak : naq; ctab = txt_cos; stab = txt_sin; srow = s;
    } else {
        nw = which ? nk : nq;   ctab = img_cos; stab = img_sin; srow = s - S_TXT;
    }

    const size_t pos = (size_t)s * DMODEL + h * HD + lane * 4;
    float4 v = *(const float4*)&buf[pos];

    float ss = v.x * v.x + v.y * v.y + v.z * v.z + v.w * v.w;
#pragma unroll
    for (int o = 16; o > 0; o >>= 1) ss += __shfl_xor_sync(0xffffffffu, ss, o);

    float inv = rsqrtf(ss * (1.0f / HD) + 1e-6f);
    float4 nwv = *(const float4*)&nw[lane * 4];
    v.x *= inv * nwv.x;
    v.y *= inv * nwv.y;
    v.z *= inv * nwv.z;
    v.w *= inv * nwv.w;

    float2 cs = *(const float2*)&ctab[(size_t)srow * (HD / 2) + lane * 2];
    float2 sn = *(const float2*)&stab[(size_t)srow * (HD / 2) + lane * 2];
    float o0 = v.x * cs.x - v.y * sn.x;
    float o1 = v.x * sn.x + v.y * cs.x;
    float o2 = v.z * cs.y - v.w * sn.y;
    float o3 = v.z * sn.y + v.w * cs.y;

    if (which == 0) {
        uint32_t h0, l0, h1, l1;
        split_pack2(o0, o1, h0, l0);
        split_pack2(o2, o3, h1, l1);
        uint2 H = {h0, h1}, L = {l0, l1};
        *(uint2*)&g_Qh[pos] = H;
        *(uint2*)&g_Ql[pos] = L;
    } else {
        uint2 H = {pack2_h(o0, o1), pack2_h(o2, o3)};
        *(uint2*)&g_Kh[pos] = H;
    }
}

// ---------------------------------------------------------------------------
// flash attention on tensor cores.
// QK^T: 2-pass (Qh+Ql vs Kh single plane), fp32-acc.
// PV:   1-pass (P fp16 single, V fp16 single), fp32-acc.
// ---------------------------------------------------------------------------
#define FQT 128
#define FKT 64
#define FLDS 136
#define FPLANE_Q (FQT * FLDS)
#define FPLANE_K (FKT * FLDS)
#define FQB (FPLANE_Q * 2)               // 34816
#define FKB (FPLANE_K * 2)               // 17408
#define FLASH_SMEM (2 * FQB + 4 * FKB)   // 139264

__device__ __forceinline__ void flash_load_kv(uint32_t dstbase, int k0,
                                              int hoff, int tid)
{
#pragma unroll
    for (int t = 0; t < 8; t++) {
        int i = tid + t * 256;          // 0..2047
        int plane = i >> 10;            // 0 Kh, 1 Vh
        int idx = i & 1023;
        int r = idx >> 4;
        int c = (idx & 15) * 8;
        const __half* g = (plane == 0) ? g_Kh : g_Vh;
        cp_async16(dstbase + (uint32_t)plane * FKB + (uint32_t)(r * FLDS + c) * 2,
                   g + (size_t)(k0 + r) * DMODEL + hoff + c);
    }
}

__global__ __launch_bounds__(256, 1) void flash_mma_kernel()
{
    const uint32_t base = smem_u32(dyn_sm);
    const int tid  = threadIdx.x;
    const int wid  = tid >> 5;
    const int lane = tid & 31;
    const int h    = blockIdx.y;
    const int hoff = h * HD;
    const int q0   = blockIdx.x * FQT;

    const uint32_t sQh = base;
    const uint32_t sKV = base + 2 * FQB;
    const float scale = 0.08838834764831845f;

#pragma unroll
    for (int t = 0; t < 16; t++) {
        int i = tid + t * 256;
        int plane = i >> 11;
        int idx = i & 2047;
        int r = idx >> 4;
        int c = (idx & 15) * 8;
        const __half* g = plane ? g_Ql : g_Qh;
        cp_async16(sQh + (uint32_t)plane * FQB + (uint32_t)(r * FLDS + c) * 2,
                   g + (size_t)(q0 + r) * DMODEL + hoff + c);
    }
    flash_load_kv(sKV, 0, hoff, tid);
    cp_commit();

    float o[16][4];
#pragma unroll
    for (int j = 0; j < 16; j++)
#pragma unroll
        for (int i = 0; i < 4; i++) o[j][i] = 0.0f;
    float m0 = -1e30f, m1 = -1e30f, l0 = 0.0f, l1 = 0.0f;

    const int wq0 = wid * 16;
    const uint32_t lrow  = lane & 15;
    const uint32_t lcolb = (lane >> 4) * 16;

    const int NKT = S_ALL / FKT;   // 44
    for (int kt = 0; kt < NKT; kt++) {
        const uint32_t bufb = sKV + (uint32_t)(kt & 1) * (2 * FKB);
        if (kt + 1 < NKT) {
            flash_load_kv(sKV + (uint32_t)((kt + 1) & 1) * (2 * FKB),
                          (kt + 1) * FKT, hoff, tid);
            cp_commit();
            cp_wait<1>();
        } else {
            cp_wait<0>();
        }
        __syncthreads();

        // ---- S = Q K^T (2-pass: Qh,Ql vs Kh; fp32-acc) ----
        float s[8][4];
#pragma unroll
        for (int j = 0; j < 8; j++)
#pragma unroll
            for (int i = 0; i < 4; i++) s[j][i] = 0.0f;

#pragma unroll
        for (int ks = 0; ks < 8; ks++) {
            uint32_t qa = sQh + (uint32_t)((wq0 + lrow) * FLDS + ks * 16) * 2 + lcolb;
            uint32_t ah[4], al[4];
            ldsm_x4(ah, qa);
            ldsm_x4(al, qa + FQB);
            uint32_t bh[8][2];
#pragma unroll
            for (int ng = 0; ng < 4; ng++) {
                uint32_t ka = bufb + (uint32_t)((ng * 16 + lrow) * FLDS + ks * 16) * 2 + lcolb;
                uint32_t rh[4];
                ldsm_x4(rh, ka);
                bh[2 * ng][0] = rh[0]; bh[2 * ng][1] = rh[2];
                bh[2 * ng + 1][0] = rh[1]; bh[2 * ng + 1][1] = rh[3];
            }
#pragma unroll
            for (int j = 0; j < 8; j++) mma16816(s[j], ah, bh[j]);
#pragma unroll
            for (int j = 0; j < 8; j++) mma16816(s[j], al, bh[j]);
        }

        // ---- online softmax (scale applied here) ----
        float mx0 = -1e30f, mx1 = -1e30f;
#pragma unroll
        for (int j = 0; j < 8; j++) {
            mx0 = fmaxf(mx0, fmaxf(s[j][0], s[j][1]));
            mx1 = fmaxf(mx1, fmaxf(s[j][2], s[j][3]));
        }
        mx0 = fmaxf(mx0, __shfl_xor_sync(0xffffffffu, mx0, 1));
        mx0 = fmaxf(mx0, __shfl_xor_sync(0xffffffffu, mx0, 2));
        mx1 = fmaxf(mx1, __shfl_xor_sync(0xffffffffu, mx1, 1));
        mx1 = fmaxf(mx1, __shfl_xor_sync(0xffffffffu, mx1, 2));
        float mn0 = fmaxf(m0, mx0);
        float mn1 = fmaxf(m1, mx1);
        float al0 = __expf((m0 - mn0) * scale);
        float al1 = __expf((m1 - mn1) * scale);
        float rs0 = 0.0f, rs1 = 0.0f;
#pragma unroll
        for (int j = 0; j < 8; j++) {
            s[j][0] = __expf((s[j][0] - mn0) * scale);
            s[j][1] = __expf((s[j][1] - mn0) * scale);
            s[j][2] = __expf((s[j][2] - mn1) * scale);
            s[j][3] = __expf((s[j][3] - mn1) * scale);
            rs0 += s[j][0] + s[j][1];
            rs1 += s[j][2] + s[j][3];
        }
        rs0 += __shfl_xor_sync(0xffffffffu, rs0, 1);
        rs0 += __shfl_xor_sync(0xffffffffu, rs0, 2);
        rs1 += __shfl_xor_sync(0xffffffffu, rs1, 1);
        rs1 += __shfl_xor_sync(0xffffffffu, rs1, 2);
        l0 = l0 * al0 + rs0;
        l1 = l1 * al1 + rs1;
        m0 = mn0;
        m1 = mn1;
#pragma unroll
        for (int j = 0; j < 16; j++) {
            o[j][0] *= al0; o[j][1] *= al0;
            o[j][2] *= al1; o[j][3] *= al1;
        }

        // ---- O += P V (1-pass: P fp16, V fp16; fp32-acc) ----
        const uint32_t Vb = bufb + FKB;
#pragma unroll
        for (int t = 0; t < 4; t++) {
            uint32_t aph[4];
            aph[0] = pack2_h(s[2 * t][0],     s[2 * t][1]);
            aph[1] = pack2_h(s[2 * t][2],     s[2 * t][3]);
            aph[2] = pack2_h(s[2 * t + 1][0], s[2 * t + 1][1]);
            aph[3] = pack2_h(s[2 * t + 1][2], s[2 * t + 1][3]);
#pragma unroll
            for (int gp = 0; gp < 4; gp++) {
                const int g0 = 2 * gp, g1 = 2 * gp + 1;
                uint32_t va0 = Vb + (uint32_t)((t * 16 + lrow) * FLDS + g0 * 16) * 2 + lcolb;
                uint32_t va1 = Vb + (uint32_t)((t * 16 + lrow) * FLDS + g1 * 16) * 2 + lcolb;
                uint32_t h0[4], h1[4];
                ldsm_x4_t(h0, va0);
                ldsm_x4_t(h1, va1);
                uint32_t bh00[2] = {h0[0], h0[1]}, bh01[2] = {h0[2], h0[3]};
                uint32_t bh10[2] = {h1[0], h1[1]}, bh11[2] = {h1[2], h1[3]};
                mma16816(o[2 * g0],     aph, bh00);
                mma16816(o[2 * g0 + 1], aph, bh01);
                mma16816(o[2 * g1],     aph, bh10);
                mma16816(o[2 * g1 + 1], aph, bh11);
            }
        }
        __syncthreads();
    }

    // ---- epilogue: normalize, store single fp16 plane ----
    float il0 = 1.0f / l0, il1 = 1.0f / l1;
    const int r0 = q0 + wq0 + (lane >> 2);
    const int r1 = r0 + 8;
    const int cb = hoff + (lane & 3) * 2;
#pragma unroll
    for (int j = 0; j < 16; j++) {
        int c = cb + j * 8;
        *(uint32_t*)&g_Oh[(size_t)r0 * DMODEL + c] =
            pack2_h(o[j][0] * il0, o[j][1] * il0);
        *(uint32_t*)&g_Oh[(size_t)r1 * DMODEL + c] =
            pack2_h(o[j][2] * il1, o[j][3] * il1);
    }
}

// ---------------------------------------------------------------------------
extern "C" void kernel_launch(void* const* d_in, const int* in_sizes, int n_in,
                              void* d_out, int out_size)
{
    const float* hid   = (const float*)d_in[0];
    const float* enc   = (const float*)d_in[1];
    const float* wq    = (const float*)d_in[2];
    const float* bq    = (const float*)d_in[3];
    const float* wk    = (const float*)d_in[4];
    const float* bk    = (const float*)d_in[5];
    const float* wv    = (const float*)d_in[6];
    const float* bv    = (const float*)d_in[7];
    const float* waq   = (const float*)d_in[8];
    const float* baq   = (const float*)d_in[9];
    const float* wak   = (const float*)d_in[10];
    const float* bak   = (const float*)d_in[11];
    const float* wav   = (const float*)d_in[12];
    const float* bav   = (const float*)d_in[13];
    const float* nq    = (const float*)d_in[14];
    const float* nk    = (const float*)d_in[15];
    const float* naq   = (const float*)d_in[16];
    const float* nak   = (const float*)d_in[17];
    const float* w_out     = (const float*)d_in[18];
    const float* b_out     = (const float*)d_in[19];
    const float* w_add_out = (const float*)d_in[20];
    const float* b_add_out = (const float*)d_in[21];
    const float* img_cos = (const float*)d_in[22];
    const float* img_sin = (const float*)d_in[23];
    const float* txt_cos = (const float*)d_in[24];
    const float* txt_sin = (const float*)d_in[25];

    float* out = (float*)d_out;

    // prepass conversions
    {
        size_t n4 = (size_t)S_ALL * DMODEL / 4;
        conv_x_kernel<<<(unsigned)((n4 + 255) / 256), 256>>>(hid, enc);
        size_t w4 = (size_t)DMODEL * DMODEL / 4;
        dim3 gw((unsigned)((w4 + 255) / 256), 8);
        conv_w_kernel<<<gw, 256>>>(wq, wk, wv, waq, wak, wav, w_out, w_add_out);
    }

    cudaFuncSetAttribute(qkv_gemm_kernel,
                         cudaFuncAttributeMaxDynamicSharedMemorySize,
                         GEMM_SMEM_BYTES);
    qkv_gemm_kernel<<<dim3(DMODEL / BN, S_ALL / BM, 3), 256, GEMM_SMEM_BYTES>>>(
        bq, bk, bv, baq, bak, bav);

    rmsrope_kernel<<<(S_ALL * NH * 2) / 8, 256>>>(nq, nk, naq, nak,
                                                  img_cos, img_sin,
                                                  txt_cos, txt_sin);

    cudaFuncSetAttribute(flash_mma_kernel,
                         cudaFuncAttributeMaxDynamicSharedMemorySize,
                         FLASH_SMEM);
    flash_mma_kernel<<<dim3(S_ALL / FQT, NH), 256, FLASH_SMEM>>>();

    cudaFuncSetAttribute(outproj_gemm_kernel,
                         cudaFuncAttributeMaxDynamicSharedMemorySize,
                         GEMM_SMEM_BYTES);
    outproj_gemm_kernel<<<dim3(DMODEL / BN, S_ALL / BM), 256, GEMM_SMEM_BYTES>>>(
        b_out, b_add_out, out);
}

// round 17
// speedup vs baseline: 1.9913x; 1.1045x over previous
#include <cuda_runtime.h>
#include <cuda_fp16.h>
#include <cstdint>
#include <math.h>

// Problem constants
#define S_TXT 512
#define S_IMG 2304
#define S_ALL 2816
#define DMODEL 3072
#define NH 24
#define HD 128

// ---------------------------------------------------------------------------
// Static device scratch (allocation-free rule)
// ---------------------------------------------------------------------------
__device__ float g_Q[S_ALL * DMODEL];
__device__ float g_K[S_ALL * DMODEL];

__device__ __half g_Xh[S_ALL * DMODEL];
__device__ __half g_Qh[S_ALL * DMODEL];
__device__ __half g_Kh[S_ALL * DMODEL];
__device__ __half g_Vh[S_ALL * DMODEL];
__device__ __half g_Oh[S_ALL * DMODEL];
// 8 weight matrices (single fp16 plane): 0=wq 1=wk 2=wv 3=waq 4=wak 5=wav 6=w_out 7=w_add_out
__device__ __half g_Wh[(size_t)8 * DMODEL * DMODEL];

// ---------------------------------------------------------------------------
// helpers
// ---------------------------------------------------------------------------
__device__ __forceinline__ uint32_t smem_u32(const void* p) {
    uint32_t a;
    asm("{ .reg .u64 t; cvta.to.shared.u64 t, %1; cvt.u32.u64 %0, t; }"
        : "=r"(a) : "l"(p));
    return a;
}

__device__ __forceinline__ void cp_async16(uint32_t dst, const void* src) {
    asm volatile("cp.async.cg.shared.global [%0], [%1], 16;"
                 :: "r"(dst), "l"(src));
}
__device__ __forceinline__ void cp_commit() {
    asm volatile("cp.async.commit_group;");
}
template <int N>
__device__ __forceinline__ void cp_wait() {
    asm volatile("cp.async.wait_group %0;" :: "n"(N));
}

__device__ __forceinline__ void ldsm_x4(uint32_t* r, uint32_t addr) {
    asm volatile("ldmatrix.sync.aligned.m8n8.x4.shared.b16 {%0,%1,%2,%3}, [%4];"
                 : "=r"(r[0]), "=r"(r[1]), "=r"(r[2]), "=r"(r[3]) : "r"(addr));
}

__device__ __forceinline__ void ldsm_x4_t(uint32_t* r, uint32_t addr) {
    asm volatile("ldmatrix.sync.aligned.m8n8.x4.trans.shared.b16 {%0,%1,%2,%3}, [%4];"
                 : "=r"(r[0]), "=r"(r[1]), "=r"(r[2]), "=r"(r[3]) : "r"(addr));
}

__device__ __forceinline__ void mma16816(float* d, const uint32_t* a,
                                         const uint32_t* b) {
    asm volatile(
        "mma.sync.aligned.m16n8k16.row.col.f32.f16.f16.f32 "
        "{%0,%1,%2,%3}, {%4,%5,%6,%7}, {%8,%9}, {%0,%1,%2,%3};"
        : "+f"(d[0]), "+f"(d[1]), "+f"(d[2]), "+f"(d[3])
        : "r"(a[0]), "r"(a[1]), "r"(a[2]), "r"(a[3]), "r"(b[0]), "r"(b[1]));
}

__device__ __forceinline__ uint32_t pack2_h(float f0, float f1)
{
    __half2 H = {__float2half_rn(f0), __float2half_rn(f1)};
    return *(uint32_t*)&H;
}

// ---------------------------------------------------------------------------
// prepass: fp32 -> fp16 for X and W
// ---------------------------------------------------------------------------
__global__ __launch_bounds__(256) void conv_x_kernel(
    const float* __restrict__ hid, const float* __restrict__ enc)
{
    size_t i = (size_t)blockIdx.x * blockDim.x + threadIdx.x;
    size_t n4 = (size_t)S_ALL * DMODEL / 4;
    if (i >= n4) return;
    size_t e = i * 4;
    size_t row = e / DMODEL;
    const float* src = (row < S_TXT) ? (enc + e)
                                     : (hid + (e - (size_t)S_TXT * DMODEL));
    float4 v = *(const float4*)src;
    uint2 H = {pack2_h(v.x, v.y), pack2_h(v.z, v.w)};
    *(uint2*)&g_Xh[e] = H;
}

__global__ __launch_bounds__(256) void conv_w_kernel(
    const float* __restrict__ w0, const float* __restrict__ w1,
    const float* __restrict__ w2, const float* __restrict__ w3,
    const float* __restrict__ w4, const float* __restrict__ w5,
    const float* __restrict__ w6, const float* __restrict__ w7)
{
    const float* ws[8] = {w0, w1, w2, w3, w4, w5, w6, w7};
    int widx = blockIdx.y;
    size_t i = (size_t)blockIdx.x * blockDim.x + threadIdx.x;
    size_t n4 = (size_t)DMODEL * DMODEL / 4;
    if (i >= n4) return;
    size_t e = i * 4;
    float4 v = *(const float4*)(ws[widx] + e);
    uint2 H = {pack2_h(v.x, v.y), pack2_h(v.z, v.w)};
    *(uint2*)&g_Wh[(size_t)widx * DMODEL * DMODEL + e] = H;
}

// ---------------------------------------------------------------------------
// mma.sync 1-pass fp16 GEMM: C[128x128] = Ah[128,K] * Bh[128,K]^T + bias
// fp32 accumulate. 3-stage cp.async pipeline, 2 CTAs/SM.
// ---------------------------------------------------------------------------
#define BM 128
#define BN 128
#define BK 32
#define LDS 40
#define ARR_HALVES (128 * LDS)             // 5120 halves / plane
#define STAGE_HALVES (2 * ARR_HALVES)      // Ah | Bh
#define NSTAGE 3
#define GEMM_SMEM_BYTES (NSTAGE * STAGE_HALVES * 2)   // 61440

extern __shared__ char dyn_sm[];

__device__ __forceinline__ void gemm_load_stage(
    uint32_t stage, const __half* __restrict__ Ah,
    const __half* __restrict__ Bh, int k0, int tid)
{
#pragma unroll
    for (int t = 0; t < 4; t++) {
        int i   = tid + t * 256;        // 0..1023
        int arr = i >> 9;               // 0..1
        int idx = i & 511;
        int row = idx >> 2;
        int c   = (idx & 3) * 8;
        const __half* g = (arr == 0) ? Ah : Bh;
        uint32_t dst = stage + (uint32_t)(arr * ARR_HALVES + row * LDS + c) * 2;
        cp_async16(dst, g + (size_t)row * DMODEL + k0 + c);
    }
}

// C != nullptr: fp32 store. else: single fp16 plane store to Ch.
__device__ __forceinline__ void gemm_tile_mma(
    const __half* __restrict__ Ah, const __half* __restrict__ Bh,
    const float* __restrict__ bias, float* __restrict__ C,
    __half* __restrict__ Ch, int ldc)
{
    const uint32_t smem_base = smem_u32(dyn_sm);
    const int tid  = threadIdx.x;
    const int wid  = tid >> 5;
    const int lane = tid & 31;
    const int wm   = wid & 3;
    const int wn   = wid >> 2;

    float d[2][8][4];
#pragma unroll
    for (int mt = 0; mt < 2; mt++)
#pragma unroll
        for (int nt = 0; nt < 8; nt++)
#pragma unroll
            for (int j = 0; j < 4; j++) d[mt][nt][j] = 0.0f;

    const int NCH = DMODEL / BK;   // 96

    gemm_load_stage(smem_base, Ah, Bh, 0, tid);
    cp_commit();
    gemm_load_stage(smem_base + (uint32_t)(STAGE_HALVES * 2), Ah, Bh, BK, tid);
    cp_commit();

    const int lrow = lane & 15;
    const int lcol = (lane >> 4) * 8;

    int sidx = 0;
    for (int kc = 0; kc < NCH; kc++) {
        if (kc + 2 < NCH) {
            int ls = sidx + 2;
            if (ls >= NSTAGE) ls -= NSTAGE;
            gemm_load_stage(smem_base + (uint32_t)ls * (STAGE_HALVES * 2),
                            Ah, Bh, (kc + 2) * BK, tid);
        }
        cp_commit();
        cp_wait<2>();
        __syncthreads();

        const uint32_t stage = smem_base + (uint32_t)sidx * (STAGE_HALVES * 2);

#pragma unroll
        for (int ks = 0; ks < 2; ks++) {
            uint32_t a_h[2][4];
#pragma unroll
            for (int mt = 0; mt < 2; mt++) {
                uint32_t addr = stage +
                    (uint32_t)((wm * 32 + mt * 16 + lrow) * LDS + ks * 16 + lcol) * 2;
                ldsm_x4(a_h[mt], addr);
            }
            uint32_t b_h[8][2];
#pragma unroll
            for (int ng = 0; ng < 4; ng++) {
                uint32_t addr = stage + (uint32_t)ARR_HALVES * 2 +
                    (uint32_t)((wn * 64 + ng * 16 + lrow) * LDS + ks * 16 + lcol) * 2;
                uint32_t r[4];
                ldsm_x4(r, addr);
                b_h[2 * ng][0] = r[0]; b_h[2 * ng][1] = r[2];
                b_h[2 * ng + 1][0] = r[1]; b_h[2 * ng + 1][1] = r[3];
            }
#pragma unroll
            for (int mt = 0; mt < 2; mt++)
#pragma unroll
                for (int nt = 0; nt < 8; nt++)
                    mma16816(d[mt][nt], a_h[mt], b_h[nt]);
        }
        __syncthreads();
        if (++sidx == NSTAGE) sidx = 0;
    }

#pragma unroll
    for (int mt = 0; mt < 2; mt++) {
        int r0 = wm * 32 + mt * 16 + (lane >> 2);
#pragma unroll
        for (int nt = 0; nt < 8; nt++) {
            int c0 = wn * 64 + nt * 8 + (lane & 3) * 2;
            float b0 = bias[c0], b1 = bias[c0 + 1];
            float v00 = d[mt][nt][0] + b0, v01 = d[mt][nt][1] + b1;
            float v10 = d[mt][nt][2] + b0, v11 = d[mt][nt][3] + b1;
            if (C != nullptr) {
                *(float2*)&C[(size_t)r0 * ldc + c0]       = make_float2(v00, v01);
                *(float2*)&C[(size_t)(r0 + 8) * ldc + c0] = make_float2(v10, v11);
            } else {
                *(uint32_t*)&Ch[(size_t)r0 * ldc + c0]       = pack2_h(v00, v01);
                *(uint32_t*)&Ch[(size_t)(r0 + 8) * ldc + c0] = pack2_h(v10, v11);
            }
        }
    }
}

__global__ __launch_bounds__(256, 2) void qkv_gemm_kernel(
    const float* __restrict__ bq,  const float* __restrict__ bk,
    const float* __restrict__ bv,  const float* __restrict__ baq,
    const float* __restrict__ bak, const float* __restrict__ bav)
{
    const int n0 = blockIdx.x * BN;
    const int m0 = blockIdx.y * BM;
    const int z  = blockIdx.z;
    const bool txt = (m0 < S_TXT);
    const int widx = txt ? (3 + z) : z;
    const float* bias = (z == 0) ? (txt ? baq : bq)
                      : (z == 1) ? (txt ? bak : bk)
                                 : (txt ? bav : bv);
    const size_t off = (size_t)m0 * DMODEL + n0;
    float* C = (z == 0) ? (g_Q + off) : (z == 1) ? (g_K + off) : nullptr;
    __half* Ch = (z == 2) ? (g_Vh + off) : nullptr;
    const size_t wb = (size_t)widx * DMODEL * DMODEL + (size_t)n0 * DMODEL;
    gemm_tile_mma(g_Xh + (size_t)m0 * DMODEL, g_Wh + wb, bias + n0, C, Ch, DMODEL);
}

__global__ __launch_bounds__(256, 2) void outproj_gemm_kernel(
    const float* __restrict__ b_out, const float* __restrict__ b_add_out,
    float* __restrict__ out)
{
    const int n0 = blockIdx.x * BN;
    const int m0 = blockIdx.y * BM;
    const bool txt = (m0 < S_TXT);
    const int widx = txt ? 7 : 6;
    const float* bias = txt ? b_add_out : b_out;
    float* C = txt ? (out + ((size_t)S_IMG + m0) * DMODEL + n0)
                   : (out + (size_t)(m0 - S_TXT) * DMODEL + n0);
    const size_t wb = (size_t)widx * DMODEL * DMODEL + (size_t)n0 * DMODEL;
    gemm_tile_mma(g_Oh + (size_t)m0 * DMODEL, g_Wh + wb, bias + n0, C, nullptr, DMODEL);
}

// ---------------------------------------------------------------------------
// per-head RMSNorm + RoPE, warp-per-head. Q and K -> single fp16 plane.
// ---------------------------------------------------------------------------
__global__ __launch_bounds__(256) void rmsrope_kernel(
    const float* __restrict__ nq,  const float* __restrict__ nk,
    const float* __restrict__ naq, const float* __restrict__ nak,
    const float* __restrict__ img_cos, const float* __restrict__ img_sin,
    const float* __restrict__ txt_cos, const float* __restrict__ txt_sin)
{
    const int item = blockIdx.x * 8 + (threadIdx.x >> 5);
    const int lane = threadIdx.x & 31;
    const int which = (item >= S_ALL * NH) ? 1 : 0;   // 0 = Q, 1 = K
    const int sh = which ? (item - S_ALL * NH) : item;
    const int s  = sh / NH;
    const int h  = sh - s * NH;

    const float* buf = which ? g_K : g_Q;
    const float *nw, *ctab, *stab;
    int srow;
    if (s < S_TXT) {
        nw = which ? nak : naq; ctab = txt_cos; stab = txt_sin; srow = s;
    } else {
        nw = which ? nk : nq;   ctab = img_cos; stab = img_sin; srow = s - S_TXT;
    }

    const size_t pos = (size_t)s * DMODEL + h * HD + lane * 4;
    float4 v = *(const float4*)&buf[pos];

    float ss = v.x * v.x + v.y * v.y + v.z * v.z + v.w * v.w;
#pragma unroll
    for (int o = 16; o > 0; o >>= 1) ss += __shfl_xor_sync(0xffffffffu, ss, o);

    float inv = rsqrtf(ss * (1.0f / HD) + 1e-6f);
    float4 nwv = *(const float4*)&nw[lane * 4];
    v.x *= inv * nwv.x;
    v.y *= inv * nwv.y;
    v.z *= inv * nwv.z;
    v.w *= inv * nwv.w;

    float2 cs = *(const float2*)&ctab[(size_t)srow * (HD / 2) + lane * 2];
    float2 sn = *(const float2*)&stab[(size_t)srow * (HD / 2) + lane * 2];
    float o0 = v.x * cs.x - v.y * sn.x;
    float o1 = v.x * sn.x + v.y * cs.x;
    float o2 = v.z * cs.y - v.w * sn.y;
    float o3 = v.z * sn.y + v.w * cs.y;

    uint2 H = {pack2_h(o0, o1), pack2_h(o2, o3)};
    if (which == 0) *(uint2*)&g_Qh[pos] = H;
    else            *(uint2*)&g_Kh[pos] = H;
}

// ---------------------------------------------------------------------------
// flash attention on tensor cores: all operands single fp16, fp32-acc.
// QK^T: 1-pass; PV: 1-pass. 2 CTAs/SM (smem 104448, regs capped 128).
// ---------------------------------------------------------------------------
#define FQT 128
#define FKT 64
#define FLDS 136
#define FPLANE_Q (FQT * FLDS)
#define FPLANE_K (FKT * FLDS)
#define FQB (FPLANE_Q * 2)               // 34816
#define FKB (FPLANE_K * 2)               // 17408
#define FLASH_SMEM (FQB + 4 * FKB)       // 104448

__device__ __forceinline__ void flash_load_kv(uint32_t dstbase, int k0,
                                              int hoff, int tid)
{
#pragma unroll
    for (int t = 0; t < 8; t++) {
        int i = tid + t * 256;          // 0..2047
        int plane = i >> 10;            // 0 Kh, 1 Vh
        int idx = i & 1023;
        int r = idx >> 4;
        int c = (idx & 15) * 8;
        const __half* g = (plane == 0) ? g_Kh : g_Vh;
        cp_async16(dstbase + (uint32_t)plane * FKB + (uint32_t)(r * FLDS + c) * 2,
                   g + (size_t)(k0 + r) * DMODEL + hoff + c);
    }
}

__global__ __launch_bounds__(256, 2) void flash_mma_kernel()
{
    const uint32_t base = smem_u32(dyn_sm);
    const int tid  = threadIdx.x;
    const int wid  = tid >> 5;
    const int lane = tid & 31;
    const int h    = blockIdx.y;
    const int hoff = h * HD;
    const int q0   = blockIdx.x * FQT;

    const uint32_t sQh = base;
    const uint32_t sKV = base + FQB;
    const float scale = 0.08838834764831845f;

#pragma unroll
    for (int t = 0; t < 8; t++) {
        int i = tid + t * 256;          // 0..2047
        int r = i >> 4;
        int c = (i & 15) * 8;
        cp_async16(sQh + (uint32_t)(r * FLDS + c) * 2,
                   g_Qh + (size_t)(q0 + r) * DMODEL + hoff + c);
    }
    flash_load_kv(sKV, 0, hoff, tid);
    cp_commit();

    float o[16][4];
#pragma unroll
    for (int j = 0; j < 16; j++)
#pragma unroll
        for (int i = 0; i < 4; i++) o[j][i] = 0.0f;
    float m0 = -1e30f, m1 = -1e30f, l0 = 0.0f, l1 = 0.0f;

    const int wq0 = wid * 16;
    const uint32_t lrow  = lane & 15;
    const uint32_t lcolb = (lane >> 4) * 16;

    const int NKT = S_ALL / FKT;   // 44
    for (int kt = 0; kt < NKT; kt++) {
        const uint32_t bufb = sKV + (uint32_t)(kt & 1) * (2 * FKB);
        if (kt + 1 < NKT) {
            flash_load_kv(sKV + (uint32_t)((kt + 1) & 1) * (2 * FKB),
                          (kt + 1) * FKT, hoff, tid);
            cp_commit();
            cp_wait<1>();
        } else {
            cp_wait<0>();
        }
        __syncthreads();

        // ---- S = Q K^T (1-pass fp16, fp32-acc) ----
        float s[8][4];
#pragma unroll
        for (int j = 0; j < 8; j++)
#pragma unroll
            for (int i = 0; i < 4; i++) s[j][i] = 0.0f;

#pragma unroll
        for (int ks = 0; ks < 8; ks++) {
            uint32_t qa = sQh + (uint32_t)((wq0 + lrow) * FLDS + ks * 16) * 2 + lcolb;
            uint32_t ah[4];
            ldsm_x4(ah, qa);
            uint32_t bh[8][2];
#pragma unroll
            for (int ng = 0; ng < 4; ng++) {
                uint32_t ka = bufb + (uint32_t)((ng * 16 + lrow) * FLDS + ks * 16) * 2 + lcolb;
                uint32_t rh[4];
                ldsm_x4(rh, ka);
                bh[2 * ng][0] = rh[0]; bh[2 * ng][1] = rh[2];
                bh[2 * ng + 1][0] = rh[1]; bh[2 * ng + 1][1] = rh[3];
            }
#pragma unroll
            for (int j = 0; j < 8; j++) mma16816(s[j], ah, bh[j]);
        }

        // ---- online softmax (scale applied here) ----
        float mx0 = -1e30f, mx1 = -1e30f;
#pragma unroll
        for (int j = 0; j < 8; j++) {
            mx0 = fmaxf(mx0, fmaxf(s[j][0], s[j][1]));
            mx1 = fmaxf(mx1, fmaxf(s[j][2], s[j][3]));
        }
        mx0 = fmaxf(mx0, __shfl_xor_sync(0xffffffffu, mx0, 1));
        mx0 = fmaxf(mx0, __shfl_xor_sync(0xffffffffu, mx0, 2));
        mx1 = fmaxf(mx1, __shfl_xor_sync(0xffffffffu, mx1, 1));
        mx1 = fmaxf(mx1, __shfl_xor_sync(0xffffffffu, mx1, 2));
        float mn0 = fmaxf(m0, mx0);
        float mn1 = fmaxf(m1, mx1);
        float al0 = __expf((m0 - mn0) * scale);
        float al1 = __expf((m1 - mn1) * scale);
        float rs0 = 0.0f, rs1 = 0.0f;
#pragma unroll
        for (int j = 0; j < 8; j++) {
            s[j][0] = __expf((s[j][0] - mn0) * scale);
            s[j][1] = __expf((s[j][1] - mn0) * scale);
            s[j][2] = __expf((s[j][2] - mn1) * scale);
            s[j][3] = __expf((s[j][3] - mn1) * scale);
            rs0 += s[j][0] + s[j][1];
            rs1 += s[j][2] + s[j][3];
        }
        rs0 += __shfl_xor_sync(0xffffffffu, rs0, 1);
        rs0 += __shfl_xor_sync(0xffffffffu, rs0, 2);
        rs1 += __shfl_xor_sync(0xffffffffu, rs1, 1);
        rs1 += __shfl_xor_sync(0xffffffffu, rs1, 2);
        l0 = l0 * al0 + rs0;
        l1 = l1 * al1 + rs1;
        m0 = mn0;
        m1 = mn1;
#pragma unroll
        for (int j = 0; j < 16; j++) {
            o[j][0] *= al0; o[j][1] *= al0;
            o[j][2] *= al1; o[j][3] *= al1;
        }

        // ---- O += P V (1-pass: P fp16, V fp16; fp32-acc) ----
        const uint32_t Vb = bufb + FKB;
#pragma unroll
        for (int t = 0; t < 4; t++) {
            uint32_t aph[4];
            aph[0] = pack2_h(s[2 * t][0],     s[2 * t][1]);
            aph[1] = pack2_h(s[2 * t][2],     s[2 * t][3]);
            aph[2] = pack2_h(s[2 * t + 1][0], s[2 * t + 1][1]);
            aph[3] = pack2_h(s[2 * t + 1][2], s[2 * t + 1][3]);
#pragma unroll
            for (int gp = 0; gp < 4; gp++) {
                const int g0 = 2 * gp, g1 = 2 * gp + 1;
                uint32_t va0 = Vb + (uint32_t)((t * 16 + lrow) * FLDS + g0 * 16) * 2 + lcolb;
                uint32_t va1 = Vb + (uint32_t)((t * 16 + lrow) * FLDS + g1 * 16) * 2 + lcolb;
                uint32_t h0[4], h1[4];
                ldsm_x4_t(h0, va0);
                ldsm_x4_t(h1, va1);
                uint32_t bh00[2] = {h0[0], h0[1]}, bh01[2] = {h0[2], h0[3]};
                uint32_t bh10[2] = {h1[0], h1[1]}, bh11[2] = {h1[2], h1[3]};
                mma16816(o[2 * g0],     aph, bh00);
                mma16816(o[2 * g0 + 1], aph, bh01);
                mma16816(o[2 * g1],     aph, bh10);
                mma16816(o[2 * g1 + 1], aph, bh11);
            }
        }
        __syncthreads();
    }

    // ---- epilogue: normalize, store single fp16 plane ----
    float il0 = 1.0f / l0, il1 = 1.0f / l1;
    const int r0 = q0 + wq0 + (lane >> 2);
    const int r1 = r0 + 8;
    const int cb = hoff + (lane & 3) * 2;
#pragma unroll
    for (int j = 0; j < 16; j++) {
        int c = cb + j * 8;
        *(uint32_t*)&g_Oh[(size_t)r0 * DMODEL + c] =
            pack2_h(o[j][0] * il0, o[j][1] * il0);
        *(uint32_t*)&g_Oh[(size_t)r1 * DMODEL + c] =
            pack2_h(o[j][2] * il1, o[j][3] * il1);
    }
}

// ---------------------------------------------------------------------------
extern "C" void kernel_launch(void* const* d_in, const int* in_sizes, int n_in,
                              void* d_out, int out_size)
{
    const float* hid   = (const float*)d_in[0];
    const float* enc   = (const float*)d_in[1];
    const float* wq    = (const float*)d_in[2];
    const float* bq    = (const float*)d_in[3];
    const float* wk    = (const float*)d_in[4];
    const float* bk    = (const float*)d_in[5];
    const float* wv    = (const float*)d_in[6];
    const float* bv    = (const float*)d_in[7];
    const float* waq   = (const float*)d_in[8];
    const float* baq   = (const float*)d_in[9];
    const float* wak   = (const float*)d_in[10];
    const float* bak   = (const float*)d_in[11];
    const float* wav   = (const float*)d_in[12];
    const float* bav   = (const float*)d_in[13];
    const float* nq    = (const float*)d_in[14];
    const float* nk    = (const float*)d_in[15];
    const float* naq   = (const float*)d_in[16];
    const float* nak   = (const float*)d_in[17];
    const float* w_out     = (const float*)d_in[18];
    const float* b_out     = (const float*)d_in[19];
    const float* w_add_out = (const float*)d_in[20];
    const float* b_add_out = (const float*)d_in[21];
    const float* img_cos = (const float*)d_in[22];
    const float* img_sin = (const float*)d_in[23];
    const float* txt_cos = (const float*)d_in[24];
    const float* txt_sin = (const float*)d_in[25];

    float* out = (float*)d_out;

    // prepass conversions
    {
        size_t n4 = (size_t)S_ALL * DMODEL / 4;
        conv_x_kernel<<<(unsigned)((n4 + 255) / 256), 256>>>(hid, enc);
        size_t w4 = (size_t)DMODEL * DMODEL / 4;
        dim3 gw((unsigned)((w4 + 255) / 256), 8);
        conv_w_kernel<<<gw, 256>>>(wq, wk, wv, waq, wak, wav, w_out, w_add_out);
    }

    cudaFuncSetAttribute(qkv_gemm_kernel,
                         cudaFuncAttributeMaxDynamicSharedMemorySize,
                         GEMM_SMEM_BYTES);
    qkv_gemm_kernel<<<dim3(DMODEL / BN, S_ALL / BM, 3), 256, GEMM_SMEM_BYTES>>>(
        bq, bk, bv, baq, bak, bav);

    rmsrope_kernel<<<(S_ALL * NH * 2) / 8, 256>>>(nq, nk, naq, nak,
                                                  img_cos, img_sin,
                                                  txt_cos, txt_sin);

    cudaFuncSetAttribute(flash_mma_kernel,
                         cudaFuncAttributeMaxDynamicSharedMemorySize,
                         FLASH_SMEM);
    flash_mma_kernel<<<dim3(S_ALL / FQT, NH), 256, FLASH_SMEM>>>();

    cudaFuncSetAttribute(outproj_gemm_kernel,
                         cudaFuncAttributeMaxDynamicSharedMemorySize,
                         GEMM_SMEM_BYTES);
    outproj_gemm_kernel<<<dim3(DMODEL / BN, S_ALL / BM), 256, GEMM_SMEM_BYTES>>>(
        b_out, b_add_out, out);
}